// round 13
// baseline (speedup 1.0000x reference)
#include <cuda_runtime.h>
#include <cuda_bf16.h>
#include <math.h>
#include <stdint.h>

// Problem constants (fixed by the reference)
#define NQ    900
#define BATCH 8
#define NTOK  (NQ*BATCH)        // 7200
#define DMODEL 256
#define HEADS 8
#define DFF   1024
#define S_TOT 19947
#define MTOK  (S_TOT*BATCH)     // 159576

// ---------------- scratch (static device arrays; no allocation) -------------
__device__ float g_qin[NTOK*DMODEL];
__device__ float g_cain[NTOK*DMODEL];
__device__ float g_qkv[NTOK*768];
__device__ float g_o  [NTOK*DMODEL];
__device__ float g_t2 [NTOK*DMODEL];
__device__ float g_off[NTOK*256];
__device__ float g_aw [NTOK*128];
__device__ float g_sx [NTOK*HEADS*16];
__device__ float g_sy [NTOK*HEADS*16];
__device__ float g_sw [NTOK*HEADS*16];
__device__ float g_val[(size_t)MTOK*DMODEL];
__device__ float g_ca [NTOK*DMODEL];
__device__ float g_t3 [NTOK*DMODEL];
__device__ float g_ffn[NTOK*DFF];

// ---------------- fast exp (FMA pipe, avoids MUFU bottleneck) ---------------
__device__ __forceinline__ float fexp(float x) {
    x = fmaxf(x, -80.f);
    float t  = x * 1.4426950408889634f;
    float fl = floorf(t);
    float f  = t - fl;
    float p  = 1.5403530e-4f;
    p = fmaf(p, f, 1.3333558e-3f);
    p = fmaf(p, f, 9.6181291e-3f);
    p = fmaf(p, f, 5.5504109e-2f);
    p = fmaf(p, f, 2.4022651e-1f);
    p = fmaf(p, f, 6.9314718e-1f);
    p = fmaf(p, f, 1.0f);
    int ei = (int)fl;
    float sc = __int_as_float((ei + 127) << 23);
    return p * sc;
}

// ---------------- bf16 split-pack helpers ------------------------------------
__device__ __forceinline__ void pairsplit(float x, float y, uint32_t& h, uint32_t& l) {
    __nv_bfloat162 hb = __floats2bfloat162_rn(x, y);
    float hx = __bfloat162float(__low2bfloat16(hb));
    float hy = __bfloat162float(__high2bfloat16(hb));
    __nv_bfloat162 lb = __floats2bfloat162_rn(x - hx, y - hy);
    h = *(uint32_t*)&hb;
    l = *(uint32_t*)&lb;
}

#define MMA_BF16(d, a, b)                                                     \
  asm volatile("mma.sync.aligned.m16n8k16.row.col.f32.bf16.bf16.f32 "         \
      "{%0,%1,%2,%3}, {%4,%5,%6,%7}, {%8,%9}, {%0,%1,%2,%3};"                 \
      : "+f"(d[0]), "+f"(d[1]), "+f"(d[2]), "+f"(d[3])                        \
      : "r"(a[0]), "r"(a[1]), "r"(a[2]), "r"(a[3]), "r"(b[0]), "r"(b[1]))

#define LDSM4(R, addr)                                                        \
  asm volatile("ldmatrix.sync.aligned.m8n8.x4.shared.b16 {%0,%1,%2,%3}, [%4];"\
      : "=r"((R)[0]), "=r"((R)[1]), "=r"((R)[2]), "=r"((R)[3]) : "r"(addr))

// ---------------- tensor-core NT GEMM:  C[n,f] = A[n,:]·W[f,:] + bias -------
// A row-major [N,K]; W row-major [F,K]. F multiple of 128, K multiple of 16.
// Compensated bf16 (2-way split, 3 mmas) => ~1e-6 relative accuracy.
// BM=BN=128, BK=16, **512 threads**, warp grid 4(m) x 4(n), warp tile 32x32.
// 16 warps = 4 per SMSP for latency hiding (the one-wave small GEMMs can't
// get it from multiple CTAs). Fragments via ldmatrix.x4 (conflict-free).
__global__ void __launch_bounds__(512, 1)
gemm_bf(const float* __restrict__ A, const float* __restrict__ W,
        const float* __restrict__ bias, const float* __restrict__ Res,
        float* __restrict__ C, int N, int F, int K, int ldc, int coff, int relu)
{
    // packed bf16x2 tiles, split hi/lo; 8 words of data per row, stride 12.
    __shared__ uint32_t Ah[2][128][12];
    __shared__ uint32_t Al[2][128][12];
    __shared__ uint32_t Bh[2][128][12];
    __shared__ uint32_t Bl[2][128][12];
    const uint32_t BUFB = 128 * 12 * 4;   // bytes per buffer

    const int t    = threadIdx.x;
    const int row0 = blockIdx.y * 128, col0 = blockIdx.x * 128;
    const int lrow = t >> 2;            // 0..127 (loader row)
    const int lk   = (t & 3) << 2;      // float offset 0,4,8,12
    const int wid  = t >> 5, lane = t & 31;
    const int wm   = (wid >> 2) * 32;   // 0,32,64,96
    const int wn   = (wid & 3) * 32;    // 0,32,64,96
    const int g    = lane >> 2, c = lane & 3;

    // ldmatrix per-lane base addresses (buffer 0)
    const uint32_t bAh = (uint32_t)__cvta_generic_to_shared(&Ah[0][0][0]);
    const uint32_t bAl = (uint32_t)__cvta_generic_to_shared(&Al[0][0][0]);
    const uint32_t bBh = (uint32_t)__cvta_generic_to_shared(&Bh[0][0][0]);
    const uint32_t bBl = (uint32_t)__cvta_generic_to_shared(&Bl[0][0][0]);
    const int arow  = lane & 15;             // A: rows 0..15 of the 16x16 frag
    const int akoff = (lane >> 4) * 16;      // +16B for k8..15 half
    uint32_t aAh[2], aAl[2];
#pragma unroll
    for (int mi = 0; mi < 2; mi++) {
        uint32_t off = (uint32_t)((wm + mi * 16 + arow) * 48 + akoff);
        aAh[mi] = bAh + off;
        aAl[mi] = bAl + off;
    }
    const int brow  = (lane & 7) + ((lane >> 4) << 3);  // n row within 16
    const int bkoff = ((lane >> 3) & 1) * 16;           // k-half byte offset
    uint32_t aBh[2], aBl[2];
#pragma unroll
    for (int njp = 0; njp < 2; njp++) {
        uint32_t off = (uint32_t)((wn + njp * 16 + brow) * 48 + bkoff);
        aBh[njp] = bBh + off;
        aBl[njp] = bBl + off;
    }

    float acc[2][4][4];
#pragma unroll
    for (int mi = 0; mi < 2; mi++)
#pragma unroll
        for (int nj = 0; nj < 4; nj++)
#pragma unroll
            for (int e = 0; e < 4; e++) acc[mi][nj][e] = 0.f;

    const int nk = K >> 4;

    auto loadA = [&](int kg, float4& u) {
        int gr = row0 + lrow;
        if (gr < N) u = *(const float4*)(A + (size_t)gr * K + kg + lk);
        else        u = make_float4(0.f, 0.f, 0.f, 0.f);
    };
    auto loadB = [&](int kg, float4& u) {
        u = *(const float4*)(W + (size_t)(col0 + lrow) * K + kg + lk);
    };
    auto storeT = [&](uint32_t (*Th)[128][12], uint32_t (*Tl)[128][12],
                      int b, float4 u) {
        uint32_t h0, h1, l0, l1;
        pairsplit(u.x, u.y, h0, l0);
        pairsplit(u.z, u.w, h1, l1);
        *(uint2*)&Th[b][lrow][(t & 3) * 2] = make_uint2(h0, h1);
        *(uint2*)&Tl[b][lrow][(t & 3) * 2] = make_uint2(l0, l1);
    };

    // --- prologue: tile 0 -> buffer 0 ---
    {
        float4 au, bu;
        loadA(0, au);
        loadB(0, bu);
        storeT(Ah, Al, 0, au);
        storeT(Bh, Bl, 0, bu);
    }
    __syncthreads();

    for (int kt = 0; kt < nk; kt++) {
        const uint32_t bo = (kt & 1) ? BUFB : 0u;
        const bool pf = (kt + 1 < nk);
        float4 au, bu;
        if (pf) {
            loadA((kt + 1) << 4, au);
            loadB((kt + 1) << 4, bu);
        }

        uint32_t ah[2][4], alr[2][4], bh[4][2], blr[4][2];
#pragma unroll
        for (int mi = 0; mi < 2; mi++) {
            LDSM4(ah[mi],  aAh[mi] + bo);
            LDSM4(alr[mi], aAl[mi] + bo);
        }
#pragma unroll
        for (int njp = 0; njp < 2; njp++) {
            uint32_t bt[4], bt2[4];
            LDSM4(bt,  aBh[njp] + bo);
            LDSM4(bt2, aBl[njp] + bo);
            bh[njp*2  ][0] = bt[0];  bh[njp*2  ][1] = bt[1];
            bh[njp*2+1][0] = bt[2];  bh[njp*2+1][1] = bt[3];
            blr[njp*2  ][0] = bt2[0]; blr[njp*2  ][1] = bt2[1];
            blr[njp*2+1][0] = bt2[2]; blr[njp*2+1][1] = bt2[3];
        }
#pragma unroll
        for (int mi = 0; mi < 2; mi++)
#pragma unroll
            for (int nj = 0; nj < 4; nj++) {
                MMA_BF16(acc[mi][nj], ah[mi],  bh[nj]);
                MMA_BF16(acc[mi][nj], alr[mi], bh[nj]);
                MMA_BF16(acc[mi][nj], ah[mi],  blr[nj]);
            }

        if (pf) {
            const int nb = (kt & 1) ^ 1;
            storeT(Ah, Al, nb, au);
            storeT(Bh, Bl, nb, bu);
        }
        __syncthreads();
    }

    // --- epilogue ---
#pragma unroll
    for (int mi = 0; mi < 2; mi++) {
#pragma unroll
        for (int h = 0; h < 2; h++) {
            int r = row0 + wm + mi * 16 + g + h * 8;
            if (r >= N) continue;
#pragma unroll
            for (int nj = 0; nj < 4; nj++) {
                int cc = col0 + wn + nj * 8 + c * 2;
                float v0 = acc[mi][nj][h * 2 + 0] + bias[cc];
                float v1 = acc[mi][nj][h * 2 + 1] + bias[cc + 1];
                if (Res) {
                    v0 += Res[(size_t)r * ldc + coff + cc];
                    v1 += Res[(size_t)r * ldc + coff + cc + 1];
                }
                if (relu) { v0 = fmaxf(v0, 0.f); v1 = fmaxf(v1, 0.f); }
                float* cp = C + (size_t)r * ldc + coff + cc;
                cp[0] = v0; cp[1] = v1;
            }
        }
    }
}

// ---------------- elementwise add (vectorized) -------------------------------
__global__ void add_kernel(const float4* __restrict__ a, const float4* __restrict__ b,
                           float4* __restrict__ o, int n4)
{
    int i = blockIdx.x * blockDim.x + threadIdx.x;
    if (i < n4) {
        float4 x = a[i], y = b[i];
        x.x += y.x; x.y += y.y; x.z += y.z; x.w += y.w;
        o[i] = x;
    }
}

// ---------------- flash self-attention, one query row / thread --------------
__global__ void __launch_bounds__(128)
attn_kernel(const float* __restrict__ qkv, float* __restrict__ o)
{
    const int bh = blockIdx.y;
    const int b = bh >> 3, h = bh & 7;
    const int qrow = blockIdx.x * 128 + threadIdx.x;
    const bool valid = qrow < NQ;

    float4 q[8];
    if (valid) {
        const float* qp = qkv + (size_t)(qrow * BATCH + b) * 768 + h * 32;
#pragma unroll
        for (int d = 0; d < 8; d++) {
            float4 v = *(const float4*)(qp + d * 4);
            const float s = 0.17677669529663687f;   // 1/sqrt(32)
            q[d].x = v.x * s; q[d].y = v.y * s; q[d].z = v.z * s; q[d].w = v.w * s;
        }
    }
    float4 acc[8];
#pragma unroll
    for (int d = 0; d < 8; d++) acc[d] = make_float4(0.f, 0.f, 0.f, 0.f);
    float mmax = -1e30f, lsum = 0.f;

    __shared__ float Ks[1024], Vs[1024];

    for (int m0 = 0; m0 < NQ; m0 += 32) {
        int nrows = min(32, NQ - m0);
        {
            int fi = threadIdx.x * 8;
            int r = fi >> 5, d0 = fi & 31;
            if (r < nrows) {
                const float* kp = qkv + (size_t)((m0 + r) * BATCH + b) * 768 + 256 + h * 32 + d0;
                *(float4*)(Ks + fi)     = *(const float4*)kp;
                *(float4*)(Ks + fi + 4) = *(const float4*)(kp + 4);
                const float* vp = kp + 256;
                *(float4*)(Vs + fi)     = *(const float4*)vp;
                *(float4*)(Vs + fi + 4) = *(const float4*)(vp + 4);
            }
        }
        __syncthreads();

        if (valid) {
            float s[32];
            float tmax = -1e30f;
            for (int j = 0; j < nrows; j++) {
                const float4* kr = (const float4*)(Ks + j * 32);
                float d0 = 0.f, d1 = 0.f, d2 = 0.f, d3 = 0.f;
#pragma unroll
                for (int d = 0; d < 8; d++) {
                    float4 kv = kr[d];
                    d0 = fmaf(q[d].x, kv.x, d0);
                    d1 = fmaf(q[d].y, kv.y, d1);
                    d2 = fmaf(q[d].z, kv.z, d2);
                    d3 = fmaf(q[d].w, kv.w, d3);
                }
                s[j] = (d0 + d1) + (d2 + d3);
                tmax = fmaxf(tmax, s[j]);
            }
            float mnew = fmaxf(mmax, tmax);
            float corr = fexp(mmax - mnew);
            lsum *= corr;
#pragma unroll
            for (int d = 0; d < 8; d++) {
                acc[d].x *= corr; acc[d].y *= corr; acc[d].z *= corr; acc[d].w *= corr;
            }
            for (int j = 0; j < nrows; j++) {
                float p = fexp(s[j] - mnew);
                lsum += p;
                const float4* vr = (const float4*)(Vs + j * 32);
#pragma unroll
                for (int d = 0; d < 8; d++) {
                    float4 vv = vr[d];
                    acc[d].x = fmaf(p, vv.x, acc[d].x);
                    acc[d].y = fmaf(p, vv.y, acc[d].y);
                    acc[d].z = fmaf(p, vv.z, acc[d].z);
                    acc[d].w = fmaf(p, vv.w, acc[d].w);
                }
            }
            mmax = mnew;
        }
        __syncthreads();
    }

    if (valid) {
        float inv = 1.f / lsum;
        float* op = o + (size_t)(qrow * BATCH + b) * DMODEL + h * 32;
#pragma unroll
        for (int d = 0; d < 8; d++) {
            float4 v;
            v.x = acc[d].x * inv; v.y = acc[d].y * inv;
            v.z = acc[d].z * inv; v.w = acc[d].w * inv;
            *(float4*)(op + d * 4) = v;
        }
    }
}

// ---------------- LayerNorm, in-place, warp per row (256 cols) --------------
__global__ void ln_kernel(float* __restrict__ x, const float* __restrict__ g,
                          const float* __restrict__ bt, int rows)
{
    int gid = blockIdx.x * blockDim.x + threadIdx.x;
    int r = gid >> 5;
    if (r >= rows) return;
    int lane = gid & 31;
    float* row = x + (size_t)r * 256;
    float v[8]; float s = 0.f;
#pragma unroll
    for (int i = 0; i < 8; i++) { v[i] = row[lane + i * 32]; s += v[i]; }
#pragma unroll
    for (int o = 16; o > 0; o >>= 1) s += __shfl_xor_sync(0xffffffffu, s, o);
    float mean = s * (1.f / 256.f);
    float vs = 0.f;
#pragma unroll
    for (int i = 0; i < 8; i++) { float d = v[i] - mean; vs = fmaf(d, d, vs); }
#pragma unroll
    for (int o = 16; o > 0; o >>= 1) vs += __shfl_xor_sync(0xffffffffu, vs, o);
    float rst = rsqrtf(vs * (1.f / 256.f) + 1e-5f);
#pragma unroll
    for (int i = 0; i < 8; i++) {
        int c = lane + i * 32;
        row[c] = (v[i] - mean) * rst * g[c] + bt[c];
    }
}

// ---------------- deform-attn sampling precompute ---------------------------
__global__ void prep_kernel(const float* __restrict__ off, const float* __restrict__ aw,
                            const float* __restrict__ ref,
                            float* __restrict__ sx, float* __restrict__ sy,
                            float* __restrict__ sw)
{
    int idx = blockIdx.x * blockDim.x + threadIdx.x;
    if (idx >= NTOK * HEADS) return;
    int n = idx >> 3, h = idx & 7;
    const float* op = off + (size_t)n * 256 + h * 32;
    const float* ap = aw  + (size_t)n * 128 + h * 16;
    const float* rp = ref + (size_t)n * 16;

    float a[16]; float mx = -1e30f;
#pragma unroll
    for (int t = 0; t < 16; t++) { a[t] = ap[t]; mx = fmaxf(mx, a[t]); }
    float ssum = 0.f;
#pragma unroll
    for (int t = 0; t < 16; t++) { a[t] = fexp(a[t] - mx); ssum += a[t]; }
    float inv = 1.f / ssum;

    const float Wd[4] = {150.f, 75.f, 38.f, 19.f};
    const float Hh[4] = {100.f, 50.f, 25.f, 13.f};
#pragma unroll
    for (int l = 0; l < 4; l++) {
        float cx = rp[l*4+0], cy = rp[l*4+1], rw = rp[l*4+2], rh = rp[l*4+3];
#pragma unroll
        for (int p = 0; p < 4; p++) {
            float ox = op[(l*4+p)*2+0], oy = op[(l*4+p)*2+1];
            float lx = fmaf(ox * 0.25f * 0.5f, rw, cx);
            float ly = fmaf(oy * 0.25f * 0.5f, rh, cy);
            int o_ = idx * 16 + l * 4 + p;
            sx[o_] = lx * Wd[l] - 0.5f;
            sy[o_] = ly * Hh[l] - 0.5f;
            sw[o_] = a[l*4+p] * inv;
        }
    }
}

// ---------------- deform-attn gather: warp per (token, head), lane = dh -----
__global__ void gather_kernel(const float* __restrict__ val,
                              const float* __restrict__ sx, const float* __restrict__ sy,
                              const float* __restrict__ sw, float* __restrict__ ca)
{
    int gtid = blockIdx.x * blockDim.x + threadIdx.x;
    int wid = gtid >> 5;
    if (wid >= NTOK * HEADS) return;
    int lane = gtid & 31;
    int n = wid >> 3, h = wid & 7;
    int b = n & 7;

    const int cW[4] = {150, 75, 38, 19};
    const int cH[4] = {100, 50, 25, 13};
    const int cS[4] = {0, 15000, 18750, 19700};

    const float* vbase = val + (size_t)b * 256 + h * 32 + lane;
    float acc = 0.f;
#pragma unroll
    for (int t = 0; t < 16; t++) {
        int l = t >> 2;
        float x = sx[wid * 16 + t];
        float y = sy[wid * 16 + t];
        float w = sw[wid * 16 + t];
        float xf = floorf(x), yf = floorf(y);
        int x0 = (int)xf, y0 = (int)yf;
        float fx = x - xf, fy = y - yf;
        int W_ = cW[l], H_ = cH[l];
#pragma unroll
        for (int dy = 0; dy < 2; dy++) {
            int yi = y0 + dy;
            if (yi < 0 || yi >= H_) continue;
            float wy = dy ? fy : (1.f - fy);
#pragma unroll
            for (int dx = 0; dx < 2; dx++) {
                int xi = x0 + dx;
                if (xi < 0 || xi >= W_) continue;
                float wx = dx ? fx : (1.f - fx);
                int s = cS[l] + yi * W_ + xi;
                acc = fmaf(w * wy * wx, __ldg(vbase + (size_t)s * (BATCH * 256)), acc);
            }
        }
    }
    ca[(size_t)n * 256 + h * 32 + lane] = acc;
}

// ---------------- launch ----------------------------------------------------
extern "C" void kernel_launch(void* const* d_in, const int* in_sizes, int n_in,
                              void* d_out, int out_size)
{
    (void)in_sizes; (void)n_in; (void)out_size;
    const float* tgt   = (const float*)d_in[0];
    const float* pos   = (const float*)d_in[1];
    const float* ref   = (const float*)d_in[2];
    const float* mem   = (const float*)d_in[3];
    const float* in_w  = (const float*)d_in[6];
    const float* in_b  = (const float*)d_in[7];
    const float* sow   = (const float*)d_in[8];
    const float* sob   = (const float*)d_in[9];
    const float* n1g   = (const float*)d_in[10];
    const float* n1b   = (const float*)d_in[11];
    const float* n2g   = (const float*)d_in[12];
    const float* n2b   = (const float*)d_in[13];
    const float* n3g   = (const float*)d_in[14];
    const float* n3b   = (const float*)d_in[15];
    const float* off_w = (const float*)d_in[16];
    const float* off_b = (const float*)d_in[17];
    const float* aw_w  = (const float*)d_in[18];
    const float* aw_b  = (const float*)d_in[19];
    const float* val_w = (const float*)d_in[20];
    const float* val_b = (const float*)d_in[21];
    const float* cow   = (const float*)d_in[22];
    const float* cob   = (const float*)d_in[23];
    const float* l1w   = (const float*)d_in[24];
    const float* l1b   = (const float*)d_in[25];
    const float* l2w   = (const float*)d_in[26];
    const float* l2b   = (const float*)d_in[27];
    float* out = (float*)d_out;

    float *qin, *cain, *qkv, *o_, *t2, *offb, *awb, *sx, *sy, *sw, *val, *ca, *t3, *ffn;
    cudaGetSymbolAddress((void**)&qin,  g_qin);
    cudaGetSymbolAddress((void**)&cain, g_cain);
    cudaGetSymbolAddress((void**)&qkv,  g_qkv);
    cudaGetSymbolAddress((void**)&o_,   g_o);
    cudaGetSymbolAddress((void**)&t2,   g_t2);
    cudaGetSymbolAddress((void**)&offb, g_off);
    cudaGetSymbolAddress((void**)&awb,  g_aw);
    cudaGetSymbolAddress((void**)&sx,   g_sx);
    cudaGetSymbolAddress((void**)&sy,   g_sy);
    cudaGetSymbolAddress((void**)&sw,   g_sw);
    cudaGetSymbolAddress((void**)&val,  g_val);
    cudaGetSymbolAddress((void**)&ca,   g_ca);
    cudaGetSymbolAddress((void**)&t3,   g_t3);
    cudaGetSymbolAddress((void**)&ffn,  g_ffn);

    // one-time stream/event setup (created on the first, non-captured call)
    static cudaStream_t s2 = nullptr;
    static cudaEvent_t ev_fork = nullptr, ev_join = nullptr;
    if (!s2) {
        cudaStreamCreateWithFlags(&s2, cudaStreamNonBlocking);
        cudaEventCreateWithFlags(&ev_fork, cudaEventDisableTiming);
        cudaEventCreateWithFlags(&ev_join, cudaEventDisableTiming);
    }

    auto gg = [](int N, int F) { return dim3((unsigned)(F / 128), (unsigned)((N + 127) / 128)); };
    const int n4 = NTOK * DMODEL / 4;

    // ---- fork: val projection GEMM runs concurrently on s2 ----
    cudaEventRecord(ev_fork, 0);
    cudaStreamWaitEvent(s2, ev_fork, 0);
    gemm_bf<<<gg(MTOK, 256), 512, 0, s2>>>(mem, val_w, val_b, nullptr, val,
                                           MTOK, 256, 256, 256, 0, 0);
    cudaEventRecord(ev_join, s2);

    // ---- main chain on the capture stream ----
    // 1) qin = tgt + pos
    add_kernel<<<(n4 + 255) / 256, 256>>>((const float4*)tgt, (const float4*)pos,
                                          (float4*)qin, n4);
    // 2-3) QKV projection: q,k from qin; v from tgt
    gemm_bf<<<gg(NTOK, 512), 512>>>(qin, in_w, in_b, nullptr, qkv,
                                    NTOK, 512, 256, 768, 0, 0);
    gemm_bf<<<gg(NTOK, 256), 512>>>(tgt, in_w + 512 * 256, in_b + 512, nullptr, qkv,
                                    NTOK, 256, 256, 768, 512, 0);
    // 4) self attention
    attn_kernel<<<dim3((NQ + 127) / 128, BATCH * HEADS), 128>>>(qkv, o_);
    // 5) out proj + residual(tgt), then LN2 -> t2
    gemm_bf<<<gg(NTOK, 256), 512>>>(o_, sow, sob, tgt, t2,
                                    NTOK, 256, 256, 256, 0, 0);
    ln_kernel<<<(NTOK * 32 + 255) / 256, 256>>>(t2, n2g, n2b, NTOK);
    // 6) cain = t2 + pos
    add_kernel<<<(n4 + 255) / 256, 256>>>((const float4*)t2, (const float4*)pos,
                                          (float4*)cain, n4);
    // 7-8) sampling offsets + attention weights from cain
    gemm_bf<<<gg(NTOK, 256), 512>>>(cain, off_w, off_b, nullptr, offb,
                                    NTOK, 256, 256, 256, 0, 0);
    gemm_bf<<<gg(NTOK, 128), 512>>>(cain, aw_w, aw_b, nullptr, awb,
                                    NTOK, 128, 256, 128, 0, 0);
    // 9) softmax + sample coords
    prep_kernel<<<(NTOK * HEADS + 255) / 256, 256>>>(offb, awb, ref, sx, sy, sw);

    // ---- join: gather needs the val projection ----
    cudaStreamWaitEvent(0, ev_join, 0);

    // 10) bilinear gather
    gather_kernel<<<(NTOK * HEADS * 32 + 255) / 256, 256>>>(val, sx, sy, sw, ca);
    // 11) ca out proj + residual(t2), LN1 -> t3
    gemm_bf<<<gg(NTOK, 256), 512>>>(ca, cow, cob, t2, t3,
                                    NTOK, 256, 256, 256, 0, 0);
    ln_kernel<<<(NTOK * 32 + 255) / 256, 256>>>(t3, n1g, n1b, NTOK);
    // 12) FFN
    gemm_bf<<<gg(NTOK, 1024), 512>>>(t3, l1w, l1b, nullptr, ffn,
                                     NTOK, 1024, 256, 1024, 0, 1);
    gemm_bf<<<gg(NTOK, 256), 512>>>(ffn, l2w, l2b, t3, out,
                                    NTOK, 256, 1024, 256, 0, 0);
    ln_kernel<<<(NTOK * 32 + 255) / 256, 256>>>(out, n3g, n3b, NTOK);
}

// round 14
// speedup vs baseline: 1.0637x; 1.0637x over previous
#include <cuda_runtime.h>
#include <cuda_fp16.h>
#include <math.h>
#include <stdint.h>

// Problem constants (fixed by the reference)
#define NQ    900
#define BATCH 8
#define NTOK  (NQ*BATCH)        // 7200
#define DMODEL 256
#define HEADS 8
#define DFF   1024
#define S_TOT 19947
#define MTOK  (S_TOT*BATCH)     // 159576

// ---------------- scratch (static device arrays; no allocation) -------------
__device__ float g_qin[NTOK*DMODEL];
__device__ float g_cain[NTOK*DMODEL];
__device__ float g_qkv[NTOK*768];
__device__ float g_o  [NTOK*DMODEL];
__device__ float g_t2 [NTOK*DMODEL];
__device__ float g_off[NTOK*256];
__device__ float g_aw [NTOK*128];
__device__ float g_sx [NTOK*HEADS*16];
__device__ float g_sy [NTOK*HEADS*16];
__device__ float g_sw [NTOK*HEADS*16];
__device__ float g_val[(size_t)MTOK*DMODEL];
__device__ float g_ca [NTOK*DMODEL];
__device__ float g_t3 [NTOK*DMODEL];
__device__ float g_ffn[NTOK*DFF];

// ---------------- fast exp (FMA pipe, avoids MUFU bottleneck) ---------------
__device__ __forceinline__ float fexp(float x) {
    x = fmaxf(x, -80.f);
    float t  = x * 1.4426950408889634f;
    float fl = floorf(t);
    float f  = t - fl;
    float p  = 1.5403530e-4f;
    p = fmaf(p, f, 1.3333558e-3f);
    p = fmaf(p, f, 9.6181291e-3f);
    p = fmaf(p, f, 5.5504109e-2f);
    p = fmaf(p, f, 2.4022651e-1f);
    p = fmaf(p, f, 6.9314718e-1f);
    p = fmaf(p, f, 1.0f);
    int ei = (int)fl;
    float sc = __int_as_float((ei + 127) << 23);
    return p * sc;
}

// ---------------- fp16 split-pack helpers ------------------------------------
// A = Ah + Al (Al exact residual); B rounded once to fp16.
__device__ __forceinline__ void pairsplit_h(float x, float y, uint32_t& h, uint32_t& l) {
    __half2 hb = __floats2half2_rn(x, y);
    float hx = __half2float(__low2half(hb));
    float hy = __half2float(__high2half(hb));
    __half2 lb = __floats2half2_rn(x - hx, y - hy);
    h = *(uint32_t*)&hb;
    l = *(uint32_t*)&lb;
}
__device__ __forceinline__ uint32_t packh(float x, float y) {
    __half2 hb = __floats2half2_rn(x, y);
    return *(uint32_t*)&hb;
}

#define MMA_F16(d, a, b)                                                      \
  asm volatile("mma.sync.aligned.m16n8k16.row.col.f32.f16.f16.f32 "           \
      "{%0,%1,%2,%3}, {%4,%5,%6,%7}, {%8,%9}, {%0,%1,%2,%3};"                 \
      : "+f"(d[0]), "+f"(d[1]), "+f"(d[2]), "+f"(d[3])                        \
      : "r"(a[0]), "r"(a[1]), "r"(a[2]), "r"(a[3]), "r"(b[0]), "r"(b[1]))

#define LDSM4(R, addr)                                                        \
  asm volatile("ldmatrix.sync.aligned.m8n8.x4.shared.b16 {%0,%1,%2,%3}, [%4];"\
      : "=r"((R)[0]), "=r"((R)[1]), "=r"((R)[2]), "=r"((R)[3]) : "r"(addr))

// ---------------- tensor-core NT GEMM:  C[n,f] = A[n,:]·W[f,:] + bias -------
// A row-major [N,K]; W row-major [F,K]. F multiple of 128, K multiple of 16.
// Compensated fp16 (A 2-way split, 2 mmas): rel err ~1e-4 (< 1e-3 gate).
// BM=BN=128, BK=16, 512 threads, warp grid 4(m) x 4(n), warp tile 32x32.
__global__ void __launch_bounds__(512, 1)
gemm_bf(const float* __restrict__ A, const float* __restrict__ W,
        const float* __restrict__ bias, const float* __restrict__ Res,
        float* __restrict__ C, int N, int F, int K, int ldc, int coff, int relu)
{
    // packed fp16x2 tiles; 8 words of data per row, stride 12 (conflict-free).
    __shared__ uint32_t Ah[2][128][12];
    __shared__ uint32_t Al[2][128][12];
    __shared__ uint32_t Bh[2][128][12];
    const uint32_t BUFB = 128 * 12 * 4;   // bytes per buffer

    const int t    = threadIdx.x;
    const int row0 = blockIdx.y * 128, col0 = blockIdx.x * 128;
    const int lrow = t >> 2;            // 0..127 (loader row)
    const int lk   = (t & 3) << 2;      // float offset 0,4,8,12
    const int wid  = t >> 5, lane = t & 31;
    const int wm   = (wid >> 2) * 32;   // 0,32,64,96
    const int wn   = (wid & 3) * 32;    // 0,32,64,96
    const int g    = lane >> 2, c = lane & 3;

    // ldmatrix per-lane base addresses (buffer 0)
    const uint32_t bAh = (uint32_t)__cvta_generic_to_shared(&Ah[0][0][0]);
    const uint32_t bAl = (uint32_t)__cvta_generic_to_shared(&Al[0][0][0]);
    const uint32_t bBh = (uint32_t)__cvta_generic_to_shared(&Bh[0][0][0]);
    const int arow  = lane & 15;             // A: rows 0..15 of the 16x16 frag
    const int akoff = (lane >> 4) * 16;      // +16B for k8..15 half
    uint32_t aAh[2], aAl[2];
#pragma unroll
    for (int mi = 0; mi < 2; mi++) {
        uint32_t off = (uint32_t)((wm + mi * 16 + arow) * 48 + akoff);
        aAh[mi] = bAh + off;
        aAl[mi] = bAl + off;
    }
    const int brow  = (lane & 7) + ((lane >> 4) << 3);  // n row within 16
    const int bkoff = ((lane >> 3) & 1) * 16;           // k-half byte offset
    uint32_t aBh[2];
#pragma unroll
    for (int njp = 0; njp < 2; njp++) {
        uint32_t off = (uint32_t)((wn + njp * 16 + brow) * 48 + bkoff);
        aBh[njp] = bBh + off;
    }

    float acc[2][4][4];
#pragma unroll
    for (int mi = 0; mi < 2; mi++)
#pragma unroll
        for (int nj = 0; nj < 4; nj++)
#pragma unroll
            for (int e = 0; e < 4; e++) acc[mi][nj][e] = 0.f;

    const int nk = K >> 4;

    auto loadA = [&](int kg, float4& u) {
        int gr = row0 + lrow;
        if (gr < N) u = *(const float4*)(A + (size_t)gr * K + kg + lk);
        else        u = make_float4(0.f, 0.f, 0.f, 0.f);
    };
    auto loadB = [&](int kg, float4& u) {
        u = *(const float4*)(W + (size_t)(col0 + lrow) * K + kg + lk);
    };
    auto storeA = [&](int b, float4 u) {
        uint32_t h0, h1, l0, l1;
        pairsplit_h(u.x, u.y, h0, l0);
        pairsplit_h(u.z, u.w, h1, l1);
        *(uint2*)&Ah[b][lrow][(t & 3) * 2] = make_uint2(h0, h1);
        *(uint2*)&Al[b][lrow][(t & 3) * 2] = make_uint2(l0, l1);
    };
    auto storeB = [&](int b, float4 u) {
        uint32_t h0 = packh(u.x, u.y);
        uint32_t h1 = packh(u.z, u.w);
        *(uint2*)&Bh[b][lrow][(t & 3) * 2] = make_uint2(h0, h1);
    };

    // --- prologue: tile 0 -> buffer 0 ---
    {
        float4 au, bu;
        loadA(0, au);
        loadB(0, bu);
        storeA(0, au);
        storeB(0, bu);
    }
    __syncthreads();

    for (int kt = 0; kt < nk; kt++) {
        const uint32_t bo = (kt & 1) ? BUFB : 0u;
        const bool pf = (kt + 1 < nk);
        float4 au, bu;
        if (pf) {
            loadA((kt + 1) << 4, au);
            loadB((kt + 1) << 4, bu);
        }

        uint32_t ah[2][4], alr[2][4], bh[4][2];
#pragma unroll
        for (int mi = 0; mi < 2; mi++) {
            LDSM4(ah[mi],  aAh[mi] + bo);
            LDSM4(alr[mi], aAl[mi] + bo);
        }
#pragma unroll
        for (int njp = 0; njp < 2; njp++) {
            uint32_t bt[4];
            LDSM4(bt, aBh[njp] + bo);
            bh[njp*2  ][0] = bt[0];  bh[njp*2  ][1] = bt[1];
            bh[njp*2+1][0] = bt[2];  bh[njp*2+1][1] = bt[3];
        }
#pragma unroll
        for (int mi = 0; mi < 2; mi++)
#pragma unroll
            for (int nj = 0; nj < 4; nj++) {
                MMA_F16(acc[mi][nj], ah[mi],  bh[nj]);
                MMA_F16(acc[mi][nj], alr[mi], bh[nj]);
            }

        if (pf) {
            const int nb = (kt & 1) ^ 1;
            storeA(nb, au);
            storeB(nb, bu);
        }
        __syncthreads();
    }

    // --- epilogue ---
#pragma unroll
    for (int mi = 0; mi < 2; mi++) {
#pragma unroll
        for (int h = 0; h < 2; h++) {
            int r = row0 + wm + mi * 16 + g + h * 8;
            if (r >= N) continue;
#pragma unroll
            for (int nj = 0; nj < 4; nj++) {
                int cc = col0 + wn + nj * 8 + c * 2;
                float v0 = acc[mi][nj][h * 2 + 0] + bias[cc];
                float v1 = acc[mi][nj][h * 2 + 1] + bias[cc + 1];
                if (Res) {
                    v0 += Res[(size_t)r * ldc + coff + cc];
                    v1 += Res[(size_t)r * ldc + coff + cc + 1];
                }
                if (relu) { v0 = fmaxf(v0, 0.f); v1 = fmaxf(v1, 0.f); }
                float* cp = C + (size_t)r * ldc + coff + cc;
                cp[0] = v0; cp[1] = v1;
            }
        }
    }
}

// ---------------- elementwise add (vectorized) -------------------------------
__global__ void add_kernel(const float4* __restrict__ a, const float4* __restrict__ b,
                           float4* __restrict__ o, int n4)
{
    int i = blockIdx.x * blockDim.x + threadIdx.x;
    if (i < n4) {
        float4 x = a[i], y = b[i];
        x.x += y.x; x.y += y.y; x.z += y.z; x.w += y.w;
        o[i] = x;
    }
}

// ---------------- flash self-attention, one query row / thread --------------
__global__ void __launch_bounds__(128)
attn_kernel(const float* __restrict__ qkv, float* __restrict__ o)
{
    const int bh = blockIdx.y;
    const int b = bh >> 3, h = bh & 7;
    const int qrow = blockIdx.x * 128 + threadIdx.x;
    const bool valid = qrow < NQ;

    float4 q[8];
    if (valid) {
        const float* qp = qkv + (size_t)(qrow * BATCH + b) * 768 + h * 32;
#pragma unroll
        for (int d = 0; d < 8; d++) {
            float4 v = *(const float4*)(qp + d * 4);
            const float s = 0.17677669529663687f;   // 1/sqrt(32)
            q[d].x = v.x * s; q[d].y = v.y * s; q[d].z = v.z * s; q[d].w = v.w * s;
        }
    }
    float4 acc[8];
#pragma unroll
    for (int d = 0; d < 8; d++) acc[d] = make_float4(0.f, 0.f, 0.f, 0.f);
    float mmax = -1e30f, lsum = 0.f;

    __shared__ float Ks[1024], Vs[1024];

    for (int m0 = 0; m0 < NQ; m0 += 32) {
        int nrows = min(32, NQ - m0);
        {
            int fi = threadIdx.x * 8;
            int r = fi >> 5, d0 = fi & 31;
            if (r < nrows) {
                const float* kp = qkv + (size_t)((m0 + r) * BATCH + b) * 768 + 256 + h * 32 + d0;
                *(float4*)(Ks + fi)     = *(const float4*)kp;
                *(float4*)(Ks + fi + 4) = *(const float4*)(kp + 4);
                const float* vp = kp + 256;
                *(float4*)(Vs + fi)     = *(const float4*)vp;
                *(float4*)(Vs + fi + 4) = *(const float4*)(vp + 4);
            }
        }
        __syncthreads();

        if (valid) {
            float s[32];
            float tmax = -1e30f;
            for (int j = 0; j < nrows; j++) {
                const float4* kr = (const float4*)(Ks + j * 32);
                float d0 = 0.f, d1 = 0.f, d2 = 0.f, d3 = 0.f;
#pragma unroll
                for (int d = 0; d < 8; d++) {
                    float4 kv = kr[d];
                    d0 = fmaf(q[d].x, kv.x, d0);
                    d1 = fmaf(q[d].y, kv.y, d1);
                    d2 = fmaf(q[d].z, kv.z, d2);
                    d3 = fmaf(q[d].w, kv.w, d3);
                }
                s[j] = (d0 + d1) + (d2 + d3);
                tmax = fmaxf(tmax, s[j]);
            }
            float mnew = fmaxf(mmax, tmax);
            float corr = fexp(mmax - mnew);
            lsum *= corr;
#pragma unroll
            for (int d = 0; d < 8; d++) {
                acc[d].x *= corr; acc[d].y *= corr; acc[d].z *= corr; acc[d].w *= corr;
            }
            for (int j = 0; j < nrows; j++) {
                float p = fexp(s[j] - mnew);
                lsum += p;
                const float4* vr = (const float4*)(Vs + j * 32);
#pragma unroll
                for (int d = 0; d < 8; d++) {
                    float4 vv = vr[d];
                    acc[d].x = fmaf(p, vv.x, acc[d].x);
                    acc[d].y = fmaf(p, vv.y, acc[d].y);
                    acc[d].z = fmaf(p, vv.z, acc[d].z);
                    acc[d].w = fmaf(p, vv.w, acc[d].w);
                }
            }
            mmax = mnew;
        }
        __syncthreads();
    }

    if (valid) {
        float inv = 1.f / lsum;
        float* op = o + (size_t)(qrow * BATCH + b) * DMODEL + h * 32;
#pragma unroll
        for (int d = 0; d < 8; d++) {
            float4 v;
            v.x = acc[d].x * inv; v.y = acc[d].y * inv;
            v.z = acc[d].z * inv; v.w = acc[d].w * inv;
            *(float4*)(op + d * 4) = v;
        }
    }
}

// ---------------- LayerNorm, in-place, warp per row (256 cols) --------------
__global__ void ln_kernel(float* __restrict__ x, const float* __restrict__ g,
                          const float* __restrict__ bt, int rows)
{
    int gid = blockIdx.x * blockDim.x + threadIdx.x;
    int r = gid >> 5;
    if (r >= rows) return;
    int lane = gid & 31;
    float* row = x + (size_t)r * 256;
    float v[8]; float s = 0.f;
#pragma unroll
    for (int i = 0; i < 8; i++) { v[i] = row[lane + i * 32]; s += v[i]; }
#pragma unroll
    for (int o = 16; o > 0; o >>= 1) s += __shfl_xor_sync(0xffffffffu, s, o);
    float mean = s * (1.f / 256.f);
    float vs = 0.f;
#pragma unroll
    for (int i = 0; i < 8; i++) { float d = v[i] - mean; vs = fmaf(d, d, vs); }
#pragma unroll
    for (int o = 16; o > 0; o >>= 1) vs += __shfl_xor_sync(0xffffffffu, vs, o);
    float rst = rsqrtf(vs * (1.f / 256.f) + 1e-5f);
#pragma unroll
    for (int i = 0; i < 8; i++) {
        int c = lane + i * 32;
        row[c] = (v[i] - mean) * rst * g[c] + bt[c];
    }
}

// ---------------- deform-attn sampling precompute ---------------------------
__global__ void prep_kernel(const float* __restrict__ off, const float* __restrict__ aw,
                            const float* __restrict__ ref,
                            float* __restrict__ sx, float* __restrict__ sy,
                            float* __restrict__ sw)
{
    int idx = blockIdx.x * blockDim.x + threadIdx.x;
    if (idx >= NTOK * HEADS) return;
    int n = idx >> 3, h = idx & 7;
    const float* op = off + (size_t)n * 256 + h * 32;
    const float* ap = aw  + (size_t)n * 128 + h * 16;
    const float* rp = ref + (size_t)n * 16;

    float a[16]; float mx = -1e30f;
#pragma unroll
    for (int t = 0; t < 16; t++) { a[t] = ap[t]; mx = fmaxf(mx, a[t]); }
    float ssum = 0.f;
#pragma unroll
    for (int t = 0; t < 16; t++) { a[t] = fexp(a[t] - mx); ssum += a[t]; }
    float inv = 1.f / ssum;

    const float Wd[4] = {150.f, 75.f, 38.f, 19.f};
    const float Hh[4] = {100.f, 50.f, 25.f, 13.f};
#pragma unroll
    for (int l = 0; l < 4; l++) {
        float cx = rp[l*4+0], cy = rp[l*4+1], rw = rp[l*4+2], rh = rp[l*4+3];
#pragma unroll
        for (int p = 0; p < 4; p++) {
            float ox = op[(l*4+p)*2+0], oy = op[(l*4+p)*2+1];
            float lx = fmaf(ox * 0.25f * 0.5f, rw, cx);
            float ly = fmaf(oy * 0.25f * 0.5f, rh, cy);
            int o_ = idx * 16 + l * 4 + p;
            sx[o_] = lx * Wd[l] - 0.5f;
            sy[o_] = ly * Hh[l] - 0.5f;
            sw[o_] = a[l*4+p] * inv;
        }
    }
}

// ---------------- deform-attn gather: warp per (token, head), lane = dh -----
__global__ void gather_kernel(const float* __restrict__ val,
                              const float* __restrict__ sx, const float* __restrict__ sy,
                              const float* __restrict__ sw, float* __restrict__ ca)
{
    int gtid = blockIdx.x * blockDim.x + threadIdx.x;
    int wid = gtid >> 5;
    if (wid >= NTOK * HEADS) return;
    int lane = gtid & 31;
    int n = wid >> 3, h = wid & 7;
    int b = n & 7;

    const int cW[4] = {150, 75, 38, 19};
    const int cH[4] = {100, 50, 25, 13};
    const int cS[4] = {0, 15000, 18750, 19700};

    const float* vbase = val + (size_t)b * 256 + h * 32 + lane;
    float acc = 0.f;
#pragma unroll
    for (int t = 0; t < 16; t++) {
        int l = t >> 2;
        float x = sx[wid * 16 + t];
        float y = sy[wid * 16 + t];
        float w = sw[wid * 16 + t];
        float xf = floorf(x), yf = floorf(y);
        int x0 = (int)xf, y0 = (int)yf;
        float fx = x - xf, fy = y - yf;
        int W_ = cW[l], H_ = cH[l];
#pragma unroll
        for (int dy = 0; dy < 2; dy++) {
            int yi = y0 + dy;
            if (yi < 0 || yi >= H_) continue;
            float wy = dy ? fy : (1.f - fy);
#pragma unroll
            for (int dx = 0; dx < 2; dx++) {
                int xi = x0 + dx;
                if (xi < 0 || xi >= W_) continue;
                float wx = dx ? fx : (1.f - fx);
                int s = cS[l] + yi * W_ + xi;
                acc = fmaf(w * wy * wx, __ldg(vbase + (size_t)s * (BATCH * 256)), acc);
            }
        }
    }
    ca[(size_t)n * 256 + h * 32 + lane] = acc;
}

// ---------------- launch ----------------------------------------------------
extern "C" void kernel_launch(void* const* d_in, const int* in_sizes, int n_in,
                              void* d_out, int out_size)
{
    (void)in_sizes; (void)n_in; (void)out_size;
    const float* tgt   = (const float*)d_in[0];
    const float* pos   = (const float*)d_in[1];
    const float* ref   = (const float*)d_in[2];
    const float* mem   = (const float*)d_in[3];
    const float* in_w  = (const float*)d_in[6];
    const float* in_b  = (const float*)d_in[7];
    const float* sow   = (const float*)d_in[8];
    const float* sob   = (const float*)d_in[9];
    const float* n1g   = (const float*)d_in[10];
    const float* n1b   = (const float*)d_in[11];
    const float* n2g   = (const float*)d_in[12];
    const float* n2b   = (const float*)d_in[13];
    const float* n3g   = (const float*)d_in[14];
    const float* n3b   = (const float*)d_in[15];
    const float* off_w = (const float*)d_in[16];
    const float* off_b = (const float*)d_in[17];
    const float* aw_w  = (const float*)d_in[18];
    const float* aw_b  = (const float*)d_in[19];
    const float* val_w = (const float*)d_in[20];
    const float* val_b = (const float*)d_in[21];
    const float* cow   = (const float*)d_in[22];
    const float* cob   = (const float*)d_in[23];
    const float* l1w   = (const float*)d_in[24];
    const float* l1b   = (const float*)d_in[25];
    const float* l2w   = (const float*)d_in[26];
    const float* l2b   = (const float*)d_in[27];
    float* out = (float*)d_out;

    float *qin, *cain, *qkv, *o_, *t2, *offb, *awb, *sx, *sy, *sw, *val, *ca, *t3, *ffn;
    cudaGetSymbolAddress((void**)&qin,  g_qin);
    cudaGetSymbolAddress((void**)&cain, g_cain);
    cudaGetSymbolAddress((void**)&qkv,  g_qkv);
    cudaGetSymbolAddress((void**)&o_,   g_o);
    cudaGetSymbolAddress((void**)&t2,   g_t2);
    cudaGetSymbolAddress((void**)&offb, g_off);
    cudaGetSymbolAddress((void**)&awb,  g_aw);
    cudaGetSymbolAddress((void**)&sx,   g_sx);
    cudaGetSymbolAddress((void**)&sy,   g_sy);
    cudaGetSymbolAddress((void**)&sw,   g_sw);
    cudaGetSymbolAddress((void**)&val,  g_val);
    cudaGetSymbolAddress((void**)&ca,   g_ca);
    cudaGetSymbolAddress((void**)&t3,   g_t3);
    cudaGetSymbolAddress((void**)&ffn,  g_ffn);

    // one-time stream/event setup (created on the first, non-captured call)
    static cudaStream_t s2 = nullptr;
    static cudaEvent_t ev_fork = nullptr, ev_join = nullptr;
    if (!s2) {
        cudaStreamCreateWithFlags(&s2, cudaStreamNonBlocking);
        cudaEventCreateWithFlags(&ev_fork, cudaEventDisableTiming);
        cudaEventCreateWithFlags(&ev_join, cudaEventDisableTiming);
    }

    auto gg = [](int N, int F) { return dim3((unsigned)(F / 128), (unsigned)((N + 127) / 128)); };
    const int n4 = NTOK * DMODEL / 4;

    // ---- fork: val projection GEMM runs concurrently on s2 ----
    cudaEventRecord(ev_fork, 0);
    cudaStreamWaitEvent(s2, ev_fork, 0);
    gemm_bf<<<gg(MTOK, 256), 512, 0, s2>>>(mem, val_w, val_b, nullptr, val,
                                           MTOK, 256, 256, 256, 0, 0);
    cudaEventRecord(ev_join, s2);

    // ---- main chain on the capture stream ----
    // 1) qin = tgt + pos
    add_kernel<<<(n4 + 255) / 256, 256>>>((const float4*)tgt, (const float4*)pos,
                                          (float4*)qin, n4);
    // 2-3) QKV projection: q,k from qin; v from tgt
    gemm_bf<<<gg(NTOK, 512), 512>>>(qin, in_w, in_b, nullptr, qkv,
                                    NTOK, 512, 256, 768, 0, 0);
    gemm_bf<<<gg(NTOK, 256), 512>>>(tgt, in_w + 512 * 256, in_b + 512, nullptr, qkv,
                                    NTOK, 256, 256, 768, 512, 0);
    // 4) self attention
    attn_kernel<<<dim3((NQ + 127) / 128, BATCH * HEADS), 128>>>(qkv, o_);
    // 5) out proj + residual(tgt), then LN2 -> t2
    gemm_bf<<<gg(NTOK, 256), 512>>>(o_, sow, sob, tgt, t2,
                                    NTOK, 256, 256, 256, 0, 0);
    ln_kernel<<<(NTOK * 32 + 255) / 256, 256>>>(t2, n2g, n2b, NTOK);
    // 6) cain = t2 + pos
    add_kernel<<<(n4 + 255) / 256, 256>>>((const float4*)t2, (const float4*)pos,
                                          (float4*)cain, n4);
    // 7-8) sampling offsets + attention weights from cain
    gemm_bf<<<gg(NTOK, 256), 512>>>(cain, off_w, off_b, nullptr, offb,
                                    NTOK, 256, 256, 256, 0, 0);
    gemm_bf<<<gg(NTOK, 128), 512>>>(cain, aw_w, aw_b, nullptr, awb,
                                    NTOK, 128, 256, 128, 0, 0);
    // 9) softmax + sample coords
    prep_kernel<<<(NTOK * HEADS + 255) / 256, 256>>>(offb, awb, ref, sx, sy, sw);

    // ---- join: gather needs the val projection ----
    cudaStreamWaitEvent(0, ev_join, 0);

    // 10) bilinear gather
    gather_kernel<<<(NTOK * HEADS * 32 + 255) / 256, 256>>>(val, sx, sy, sw, ca);
    // 11) ca out proj + residual(t2), LN1 -> t3
    gemm_bf<<<gg(NTOK, 256), 512>>>(ca, cow, cob, t2, t3,
                                    NTOK, 256, 256, 256, 0, 0);
    ln_kernel<<<(NTOK * 32 + 255) / 256, 256>>>(t3, n1g, n1b, NTOK);
    // 12) FFN
    gemm_bf<<<gg(NTOK, 1024), 512>>>(t3, l1w, l1b, nullptr, ffn,
                                     NTOK, 1024, 256, 1024, 0, 1);
    gemm_bf<<<gg(NTOK, 256), 512>>>(ffn, l2w, l2b, t3, out,
                                    NTOK, 256, 1024, 256, 0, 0);
    ln_kernel<<<(NTOK * 32 + 255) / 256, 256>>>(out, n3g, n3b, NTOK);
}

// round 15
// speedup vs baseline: 1.1017x; 1.0357x over previous
#include <cuda_runtime.h>
#include <cuda_fp16.h>
#include <math.h>
#include <stdint.h>

// Problem constants (fixed by the reference)
#define NQ    900
#define BATCH 8
#define NTOK  (NQ*BATCH)        // 7200
#define DMODEL 256
#define HEADS 8
#define DFF   1024
#define S_TOT 19947
#define MTOK  (S_TOT*BATCH)     // 159576

// ---------------- scratch (static device arrays; no allocation) -------------
__device__ float g_qin[NTOK*DMODEL];
__device__ float g_cain[NTOK*DMODEL];
__device__ float g_qkv[NTOK*768];
__device__ float g_o  [NTOK*DMODEL];
__device__ float g_t2 [NTOK*DMODEL];
__device__ float g_off[NTOK*256];
__device__ float g_aw [NTOK*128];
__device__ float g_sx [NTOK*HEADS*16];
__device__ float g_sy [NTOK*HEADS*16];
__device__ float g_sw [NTOK*HEADS*16];
__device__ float g_val[(size_t)MTOK*DMODEL];
__device__ float g_ca [NTOK*DMODEL];
__device__ float g_t3 [NTOK*DMODEL];
__device__ float g_ffn[NTOK*DFF];

// ---------------- fast exp (FMA pipe, avoids MUFU bottleneck) ---------------
__device__ __forceinline__ float fexp(float x) {
    x = fmaxf(x, -80.f);
    float t  = x * 1.4426950408889634f;
    float fl = floorf(t);
    float f  = t - fl;
    float p  = 1.5403530e-4f;
    p = fmaf(p, f, 1.3333558e-3f);
    p = fmaf(p, f, 9.6181291e-3f);
    p = fmaf(p, f, 5.5504109e-2f);
    p = fmaf(p, f, 2.4022651e-1f);
    p = fmaf(p, f, 6.9314718e-1f);
    p = fmaf(p, f, 1.0f);
    int ei = (int)fl;
    float sc = __int_as_float((ei + 127) << 23);
    return p * sc;
}

// ---------------- fp16 split-pack helpers ------------------------------------
__device__ __forceinline__ void pairsplit_h(float x, float y, uint32_t& h, uint32_t& l) {
    __half2 hb = __floats2half2_rn(x, y);
    float hx = __half2float(__low2half(hb));
    float hy = __half2float(__high2half(hb));
    __half2 lb = __floats2half2_rn(x - hx, y - hy);
    h = *(uint32_t*)&hb;
    l = *(uint32_t*)&lb;
}
__device__ __forceinline__ uint32_t packh(float x, float y) {
    __half2 hb = __floats2half2_rn(x, y);
    return *(uint32_t*)&hb;
}

#define MMA_F16(d, a, b)                                                      \
  asm volatile("mma.sync.aligned.m16n8k16.row.col.f32.f16.f16.f32 "           \
      "{%0,%1,%2,%3}, {%4,%5,%6,%7}, {%8,%9}, {%0,%1,%2,%3};"                 \
      : "+f"(d[0]), "+f"(d[1]), "+f"(d[2]), "+f"(d[3])                        \
      : "r"(a[0]), "r"(a[1]), "r"(a[2]), "r"(a[3]), "r"(b[0]), "r"(b[1]))

#define LDSM4(R, addr)                                                        \
  asm volatile("ldmatrix.sync.aligned.m8n8.x4.shared.b16 {%0,%1,%2,%3}, [%4];"\
      : "=r"((R)[0]), "=r"((R)[1]), "=r"((R)[2]), "=r"((R)[3]) : "r"(addr))

// ---------------- tensor-core NT GEMM:  C[n,f] = A[n,:]·W[f,:] + bias -------
// A row-major [N,K]; W row-major [F,K]. F multiple of 128, K multiple of 32.
// Compensated fp16 (A 2-way split, 2 mmas): rel err ~5e-5 (< 1e-3 gate).
// BM=BN=128, BK=32 (two 16-wide sub-chunks, one barrier per 32-k),
// 512 threads, warp grid 4(m) x 4(n), warp tile 32x32.
// Dynamic smem: Ah/Al/Bh x [2 buf][2 sub][128][12 words] = 73728 B.
#define GEMM_SMEM 73728
#define CHW 1536              // words per (buf,sub) chunk = 128*12
#define CHB 6144              // bytes per chunk
__global__ void __launch_bounds__(512, 1)
gemm_bf(const float* __restrict__ A, const float* __restrict__ W,
        const float* __restrict__ bias, const float* __restrict__ Res,
        float* __restrict__ C, int N, int F, int K, int ldc, int coff, int relu)
{
    extern __shared__ uint32_t dyn[];
    uint32_t* AhP = dyn;              // 4 chunks
    uint32_t* AlP = dyn + 4 * CHW;
    uint32_t* BhP = dyn + 8 * CHW;

    const int t    = threadIdx.x;
    const int row0 = blockIdx.y * 128, col0 = blockIdx.x * 128;
    const int lrow = t >> 2;            // 0..127 (loader row)
    const int lk   = (t & 3) << 2;      // float offset 0,4,8,12 within sub
    const int wid  = t >> 5, lane = t & 31;
    const int wm   = (wid >> 2) * 32;   // 0,32,64,96
    const int wn   = (wid & 3) * 32;    // 0,32,64,96
    const int g    = lane >> 2, c = lane & 3;

    // ldmatrix per-lane base addresses (chunk-relative)
    const uint32_t bAh = (uint32_t)__cvta_generic_to_shared(AhP);
    const uint32_t bAl = (uint32_t)__cvta_generic_to_shared(AlP);
    const uint32_t bBh = (uint32_t)__cvta_generic_to_shared(BhP);
    const int arow  = lane & 15;
    const int akoff = (lane >> 4) * 16;
    uint32_t aAh[2], aAl[2];
#pragma unroll
    for (int mi = 0; mi < 2; mi++) {
        uint32_t off = (uint32_t)((wm + mi * 16 + arow) * 48 + akoff);
        aAh[mi] = bAh + off;
        aAl[mi] = bAl + off;
    }
    const int brow  = (lane & 7) + ((lane >> 4) << 3);
    const int bkoff = ((lane >> 3) & 1) * 16;
    uint32_t aBh[2];
#pragma unroll
    for (int njp = 0; njp < 2; njp++) {
        uint32_t off = (uint32_t)((wn + njp * 16 + brow) * 48 + bkoff);
        aBh[njp] = bBh + off;
    }

    float acc[2][4][4];
#pragma unroll
    for (int mi = 0; mi < 2; mi++)
#pragma unroll
        for (int nj = 0; nj < 4; nj++)
#pragma unroll
            for (int e = 0; e < 4; e++) acc[mi][nj][e] = 0.f;

    const int nk = K >> 5;              // BK=32 iterations

    auto loadA = [&](int kg, int s, float4& u) {
        int gr = row0 + lrow;
        if (gr < N) u = *(const float4*)(A + (size_t)gr * K + kg + s * 16 + lk);
        else        u = make_float4(0.f, 0.f, 0.f, 0.f);
    };
    auto loadB = [&](int kg, int s, float4& u) {
        u = *(const float4*)(W + (size_t)(col0 + lrow) * K + kg + s * 16 + lk);
    };
    auto storeA = [&](int buf, int s, float4 u) {
        uint32_t h0, h1, l0, l1;
        pairsplit_h(u.x, u.y, h0, l0);
        pairsplit_h(u.z, u.w, h1, l1);
        int co = (buf * 2 + s) * CHW + lrow * 12 + (t & 3) * 2;
        *(uint2*)&AhP[co] = make_uint2(h0, h1);
        *(uint2*)&AlP[co] = make_uint2(l0, l1);
    };
    auto storeB = [&](int buf, int s, float4 u) {
        int co = (buf * 2 + s) * CHW + lrow * 12 + (t & 3) * 2;
        *(uint2*)&BhP[co] = make_uint2(packh(u.x, u.y), packh(u.z, u.w));
    };

    // --- prologue: k-chunk 0 (both subs) -> buffer 0 ---
    {
        float4 au, bu;
#pragma unroll
        for (int s = 0; s < 2; s++) {
            loadA(0, s, au);
            loadB(0, s, bu);
            storeA(0, s, au);
            storeB(0, s, bu);
        }
    }
    __syncthreads();

    for (int kt = 0; kt < nk; kt++) {
        const int buf = kt & 1;
        const bool pf = (kt + 1 < nk);
        float4 au[2], bu[2];
        if (pf) {
            int kg = (kt + 1) << 5;
#pragma unroll
            for (int s = 0; s < 2; s++) {
                loadA(kg, s, au[s]);
                loadB(kg, s, bu[s]);
            }
        }

#pragma unroll
        for (int s = 0; s < 2; s++) {
            const uint32_t co = (uint32_t)(buf * 2 + s) * CHB;
            uint32_t ah[2][4], alr[2][4], bh[4][2];
#pragma unroll
            for (int mi = 0; mi < 2; mi++) {
                LDSM4(ah[mi],  aAh[mi] + co);
                LDSM4(alr[mi], aAl[mi] + co);
            }
#pragma unroll
            for (int njp = 0; njp < 2; njp++) {
                uint32_t bt[4];
                LDSM4(bt, aBh[njp] + co);
                bh[njp*2  ][0] = bt[0];  bh[njp*2  ][1] = bt[1];
                bh[njp*2+1][0] = bt[2];  bh[njp*2+1][1] = bt[3];
            }
#pragma unroll
            for (int mi = 0; mi < 2; mi++)
#pragma unroll
                for (int nj = 0; nj < 4; nj++) {
                    MMA_F16(acc[mi][nj], ah[mi],  bh[nj]);
                    MMA_F16(acc[mi][nj], alr[mi], bh[nj]);
                }
        }

        if (pf) {
            const int nb = buf ^ 1;
#pragma unroll
            for (int s = 0; s < 2; s++) {
                storeA(nb, s, au[s]);
                storeB(nb, s, bu[s]);
            }
        }
        __syncthreads();
    }

    // --- epilogue ---
#pragma unroll
    for (int mi = 0; mi < 2; mi++) {
#pragma unroll
        for (int h = 0; h < 2; h++) {
            int r = row0 + wm + mi * 16 + g + h * 8;
            if (r >= N) continue;
#pragma unroll
            for (int nj = 0; nj < 4; nj++) {
                int cc = col0 + wn + nj * 8 + c * 2;
                float v0 = acc[mi][nj][h * 2 + 0] + bias[cc];
                float v1 = acc[mi][nj][h * 2 + 1] + bias[cc + 1];
                if (Res) {
                    v0 += Res[(size_t)r * ldc + coff + cc];
                    v1 += Res[(size_t)r * ldc + coff + cc + 1];
                }
                if (relu) { v0 = fmaxf(v0, 0.f); v1 = fmaxf(v1, 0.f); }
                float* cp = C + (size_t)r * ldc + coff + cc;
                cp[0] = v0; cp[1] = v1;
            }
        }
    }
}

// ---------------- elementwise add (vectorized) -------------------------------
__global__ void add_kernel(const float4* __restrict__ a, const float4* __restrict__ b,
                           float4* __restrict__ o, int n4)
{
    int i = blockIdx.x * blockDim.x + threadIdx.x;
    if (i < n4) {
        float4 x = a[i], y = b[i];
        x.x += y.x; x.y += y.y; x.z += y.z; x.w += y.w;
        o[i] = x;
    }
}

// ---------------- flash self-attention, one query row / thread --------------
__global__ void __launch_bounds__(128)
attn_kernel(const float* __restrict__ qkv, float* __restrict__ o)
{
    const int bh = blockIdx.y;
    const int b = bh >> 3, h = bh & 7;
    const int qrow = blockIdx.x * 128 + threadIdx.x;
    const bool valid = qrow < NQ;

    float4 q[8];
    if (valid) {
        const float* qp = qkv + (size_t)(qrow * BATCH + b) * 768 + h * 32;
#pragma unroll
        for (int d = 0; d < 8; d++) {
            float4 v = *(const float4*)(qp + d * 4);
            const float s = 0.17677669529663687f;   // 1/sqrt(32)
            q[d].x = v.x * s; q[d].y = v.y * s; q[d].z = v.z * s; q[d].w = v.w * s;
        }
    }
    float4 acc[8];
#pragma unroll
    for (int d = 0; d < 8; d++) acc[d] = make_float4(0.f, 0.f, 0.f, 0.f);
    float mmax = -1e30f, lsum = 0.f;

    __shared__ float Ks[1024], Vs[1024];

    for (int m0 = 0; m0 < NQ; m0 += 32) {
        int nrows = min(32, NQ - m0);
        {
            int fi = threadIdx.x * 8;
            int r = fi >> 5, d0 = fi & 31;
            if (r < nrows) {
                const float* kp = qkv + (size_t)((m0 + r) * BATCH + b) * 768 + 256 + h * 32 + d0;
                *(float4*)(Ks + fi)     = *(const float4*)kp;
                *(float4*)(Ks + fi + 4) = *(const float4*)(kp + 4);
                const float* vp = kp + 256;
                *(float4*)(Vs + fi)     = *(const float4*)vp;
                *(float4*)(Vs + fi + 4) = *(const float4*)(vp + 4);
            }
        }
        __syncthreads();

        if (valid) {
            float s[32];
            float tmax = -1e30f;
            for (int j = 0; j < nrows; j++) {
                const float4* kr = (const float4*)(Ks + j * 32);
                float d0 = 0.f, d1 = 0.f, d2 = 0.f, d3 = 0.f;
#pragma unroll
                for (int d = 0; d < 8; d++) {
                    float4 kv = kr[d];
                    d0 = fmaf(q[d].x, kv.x, d0);
                    d1 = fmaf(q[d].y, kv.y, d1);
                    d2 = fmaf(q[d].z, kv.z, d2);
                    d3 = fmaf(q[d].w, kv.w, d3);
                }
                s[j] = (d0 + d1) + (d2 + d3);
                tmax = fmaxf(tmax, s[j]);
            }
            float mnew = fmaxf(mmax, tmax);
            float corr = fexp(mmax - mnew);
            lsum *= corr;
#pragma unroll
            for (int d = 0; d < 8; d++) {
                acc[d].x *= corr; acc[d].y *= corr; acc[d].z *= corr; acc[d].w *= corr;
            }
            for (int j = 0; j < nrows; j++) {
                float p = fexp(s[j] - mnew);
                lsum += p;
                const float4* vr = (const float4*)(Vs + j * 32);
#pragma unroll
                for (int d = 0; d < 8; d++) {
                    float4 vv = vr[d];
                    acc[d].x = fmaf(p, vv.x, acc[d].x);
                    acc[d].y = fmaf(p, vv.y, acc[d].y);
                    acc[d].z = fmaf(p, vv.z, acc[d].z);
                    acc[d].w = fmaf(p, vv.w, acc[d].w);
                }
            }
            mmax = mnew;
        }
        __syncthreads();
    }

    if (valid) {
        float inv = 1.f / lsum;
        float* op = o + (size_t)(qrow * BATCH + b) * DMODEL + h * 32;
#pragma unroll
        for (int d = 0; d < 8; d++) {
            float4 v;
            v.x = acc[d].x * inv; v.y = acc[d].y * inv;
            v.z = acc[d].z * inv; v.w = acc[d].w * inv;
            *(float4*)(op + d * 4) = v;
        }
    }
}

// ---------------- LayerNorm, in-place, warp per row (256 cols) --------------
__global__ void ln_kernel(float* __restrict__ x, const float* __restrict__ g,
                          const float* __restrict__ bt, int rows)
{
    int gid = blockIdx.x * blockDim.x + threadIdx.x;
    int r = gid >> 5;
    if (r >= rows) return;
    int lane = gid & 31;
    float* row = x + (size_t)r * 256;
    float v[8]; float s = 0.f;
#pragma unroll
    for (int i = 0; i < 8; i++) { v[i] = row[lane + i * 32]; s += v[i]; }
#pragma unroll
    for (int o = 16; o > 0; o >>= 1) s += __shfl_xor_sync(0xffffffffu, s, o);
    float mean = s * (1.f / 256.f);
    float vs = 0.f;
#pragma unroll
    for (int i = 0; i < 8; i++) { float d = v[i] - mean; vs = fmaf(d, d, vs); }
#pragma unroll
    for (int o = 16; o > 0; o >>= 1) vs += __shfl_xor_sync(0xffffffffu, vs, o);
    float rst = rsqrtf(vs * (1.f / 256.f) + 1e-5f);
#pragma unroll
    for (int i = 0; i < 8; i++) {
        int c = lane + i * 32;
        row[c] = (v[i] - mean) * rst * g[c] + bt[c];
    }
}

// ---------------- deform-attn sampling precompute ---------------------------
__global__ void prep_kernel(const float* __restrict__ off, const float* __restrict__ aw,
                            const float* __restrict__ ref,
                            float* __restrict__ sx, float* __restrict__ sy,
                            float* __restrict__ sw)
{
    int idx = blockIdx.x * blockDim.x + threadIdx.x;
    if (idx >= NTOK * HEADS) return;
    int n = idx >> 3, h = idx & 7;
    const float* op = off + (size_t)n * 256 + h * 32;
    const float* ap = aw  + (size_t)n * 128 + h * 16;
    const float* rp = ref + (size_t)n * 16;

    float a[16]; float mx = -1e30f;
#pragma unroll
    for (int t = 0; t < 16; t++) { a[t] = ap[t]; mx = fmaxf(mx, a[t]); }
    float ssum = 0.f;
#pragma unroll
    for (int t = 0; t < 16; t++) { a[t] = fexp(a[t] - mx); ssum += a[t]; }
    float inv = 1.f / ssum;

    const float Wd[4] = {150.f, 75.f, 38.f, 19.f};
    const float Hh[4] = {100.f, 50.f, 25.f, 13.f};
#pragma unroll
    for (int l = 0; l < 4; l++) {
        float cx = rp[l*4+0], cy = rp[l*4+1], rw = rp[l*4+2], rh = rp[l*4+3];
#pragma unroll
        for (int p = 0; p < 4; p++) {
            float ox = op[(l*4+p)*2+0], oy = op[(l*4+p)*2+1];
            float lx = fmaf(ox * 0.25f * 0.5f, rw, cx);
            float ly = fmaf(oy * 0.25f * 0.5f, rh, cy);
            int o_ = idx * 16 + l * 4 + p;
            sx[o_] = lx * Wd[l] - 0.5f;
            sy[o_] = ly * Hh[l] - 0.5f;
            sw[o_] = a[l*4+p] * inv;
        }
    }
}

// ---------------- deform-attn gather: warp per (token, head), lane = dh -----
__global__ void gather_kernel(const float* __restrict__ val,
                              const float* __restrict__ sx, const float* __restrict__ sy,
                              const float* __restrict__ sw, float* __restrict__ ca)
{
    int gtid = blockIdx.x * blockDim.x + threadIdx.x;
    int wid = gtid >> 5;
    if (wid >= NTOK * HEADS) return;
    int lane = gtid & 31;
    int n = wid >> 3, h = wid & 7;
    int b = n & 7;

    const int cW[4] = {150, 75, 38, 19};
    const int cH[4] = {100, 50, 25, 13};
    const int cS[4] = {0, 15000, 18750, 19700};

    const float* vbase = val + (size_t)b * 256 + h * 32 + lane;
    float acc = 0.f;
#pragma unroll
    for (int t = 0; t < 16; t++) {
        int l = t >> 2;
        float x = sx[wid * 16 + t];
        float y = sy[wid * 16 + t];
        float w = sw[wid * 16 + t];
        float xf = floorf(x), yf = floorf(y);
        int x0 = (int)xf, y0 = (int)yf;
        float fx = x - xf, fy = y - yf;
        int W_ = cW[l], H_ = cH[l];
#pragma unroll
        for (int dy = 0; dy < 2; dy++) {
            int yi = y0 + dy;
            if (yi < 0 || yi >= H_) continue;
            float wy = dy ? fy : (1.f - fy);
#pragma unroll
            for (int dx = 0; dx < 2; dx++) {
                int xi = x0 + dx;
                if (xi < 0 || xi >= W_) continue;
                float wx = dx ? fx : (1.f - fx);
                int s = cS[l] + yi * W_ + xi;
                acc = fmaf(w * wy * wx, __ldg(vbase + (size_t)s * (BATCH * 256)), acc);
            }
        }
    }
    ca[(size_t)n * 256 + h * 32 + lane] = acc;
}

// ---------------- launch ----------------------------------------------------
extern "C" void kernel_launch(void* const* d_in, const int* in_sizes, int n_in,
                              void* d_out, int out_size)
{
    (void)in_sizes; (void)n_in; (void)out_size;
    const float* tgt   = (const float*)d_in[0];
    const float* pos   = (const float*)d_in[1];
    const float* ref   = (const float*)d_in[2];
    const float* mem   = (const float*)d_in[3];
    const float* in_w  = (const float*)d_in[6];
    const float* in_b  = (const float*)d_in[7];
    const float* sow   = (const float*)d_in[8];
    const float* sob   = (const float*)d_in[9];
    const float* n1g   = (const float*)d_in[10];
    const float* n1b   = (const float*)d_in[11];
    const float* n2g   = (const float*)d_in[12];
    const float* n2b   = (const float*)d_in[13];
    const float* n3g   = (const float*)d_in[14];
    const float* n3b   = (const float*)d_in[15];
    const float* off_w = (const float*)d_in[16];
    const float* off_b = (const float*)d_in[17];
    const float* aw_w  = (const float*)d_in[18];
    const float* aw_b  = (const float*)d_in[19];
    const float* val_w = (const float*)d_in[20];
    const float* val_b = (const float*)d_in[21];
    const float* cow   = (const float*)d_in[22];
    const float* cob   = (const float*)d_in[23];
    const float* l1w   = (const float*)d_in[24];
    const float* l1b   = (const float*)d_in[25];
    const float* l2w   = (const float*)d_in[26];
    const float* l2b   = (const float*)d_in[27];
    float* out = (float*)d_out;

    float *qin, *cain, *qkv, *o_, *t2, *offb, *awb, *sx, *sy, *sw, *val, *ca, *t3, *ffn;
    cudaGetSymbolAddress((void**)&qin,  g_qin);
    cudaGetSymbolAddress((void**)&cain, g_cain);
    cudaGetSymbolAddress((void**)&qkv,  g_qkv);
    cudaGetSymbolAddress((void**)&o_,   g_o);
    cudaGetSymbolAddress((void**)&t2,   g_t2);
    cudaGetSymbolAddress((void**)&offb, g_off);
    cudaGetSymbolAddress((void**)&awb,  g_aw);
    cudaGetSymbolAddress((void**)&sx,   g_sx);
    cudaGetSymbolAddress((void**)&sy,   g_sy);
    cudaGetSymbolAddress((void**)&sw,   g_sw);
    cudaGetSymbolAddress((void**)&val,  g_val);
    cudaGetSymbolAddress((void**)&ca,   g_ca);
    cudaGetSymbolAddress((void**)&t3,   g_t3);
    cudaGetSymbolAddress((void**)&ffn,  g_ffn);

    // one-time stream/event/attr setup (first, non-captured call)
    static cudaStream_t s2 = nullptr;
    static cudaEvent_t ev_fork = nullptr, ev_join = nullptr;
    if (!s2) {
        cudaStreamCreateWithFlags(&s2, cudaStreamNonBlocking);
        cudaEventCreateWithFlags(&ev_fork, cudaEventDisableTiming);
        cudaEventCreateWithFlags(&ev_join, cudaEventDisableTiming);
        cudaFuncSetAttribute(gemm_bf, cudaFuncAttributeMaxDynamicSharedMemorySize,
                             GEMM_SMEM);
    }

    auto gg = [](int N, int F) { return dim3((unsigned)(F / 128), (unsigned)((N + 127) / 128)); };
    const int n4 = NTOK * DMODEL / 4;

    // ---- fork: val projection GEMM runs concurrently on s2 ----
    cudaEventRecord(ev_fork, 0);
    cudaStreamWaitEvent(s2, ev_fork, 0);
    gemm_bf<<<gg(MTOK, 256), 512, GEMM_SMEM, s2>>>(mem, val_w, val_b, nullptr, val,
                                                   MTOK, 256, 256, 256, 0, 0);
    cudaEventRecord(ev_join, s2);

    // ---- main chain on the capture stream ----
    // 1) qin = tgt + pos
    add_kernel<<<(n4 + 255) / 256, 256>>>((const float4*)tgt, (const float4*)pos,
                                          (float4*)qin, n4);
    // 2-3) QKV projection: q,k from qin; v from tgt
    gemm_bf<<<gg(NTOK, 512), 512, GEMM_SMEM>>>(qin, in_w, in_b, nullptr, qkv,
                                               NTOK, 512, 256, 768, 0, 0);
    gemm_bf<<<gg(NTOK, 256), 512, GEMM_SMEM>>>(tgt, in_w + 512 * 256, in_b + 512, nullptr, qkv,
                                               NTOK, 256, 256, 768, 512, 0);
    // 4) self attention
    attn_kernel<<<dim3((NQ + 127) / 128, BATCH * HEADS), 128>>>(qkv, o_);
    // 5) out proj + residual(tgt), then LN2 -> t2
    gemm_bf<<<gg(NTOK, 256), 512, GEMM_SMEM>>>(o_, sow, sob, tgt, t2,
                                               NTOK, 256, 256, 256, 0, 0);
    ln_kernel<<<(NTOK * 32 + 255) / 256, 256>>>(t2, n2g, n2b, NTOK);
    // 6) cain = t2 + pos
    add_kernel<<<(n4 + 255) / 256, 256>>>((const float4*)t2, (const float4*)pos,
                                          (float4*)cain, n4);
    // 7-8) sampling offsets + attention weights from cain
    gemm_bf<<<gg(NTOK, 256), 512, GEMM_SMEM>>>(cain, off_w, off_b, nullptr, offb,
                                               NTOK, 256, 256, 256, 0, 0);
    gemm_bf<<<gg(NTOK, 128), 512, GEMM_SMEM>>>(cain, aw_w, aw_b, nullptr, awb,
                                               NTOK, 128, 256, 128, 0, 0);
    // 9) softmax + sample coords
    prep_kernel<<<(NTOK * HEADS + 255) / 256, 256>>>(offb, awb, ref, sx, sy, sw);

    // ---- join: gather needs the val projection ----
    cudaStreamWaitEvent(0, ev_join, 0);

    // 10) bilinear gather
    gather_kernel<<<(NTOK * HEADS * 32 + 255) / 256, 256>>>(val, sx, sy, sw, ca);
    // 11) ca out proj + residual(t2), LN1 -> t3
    gemm_bf<<<gg(NTOK, 256), 512, GEMM_SMEM>>>(ca, cow, cob, t2, t3,
                                               NTOK, 256, 256, 256, 0, 0);
    ln_kernel<<<(NTOK * 32 + 255) / 256, 256>>>(t3, n1g, n1b, NTOK);
    // 12) FFN
    gemm_bf<<<gg(NTOK, 1024), 512, GEMM_SMEM>>>(t3, l1w, l1b, nullptr, ffn,
                                                NTOK, 1024, 256, 1024, 0, 1);
    gemm_bf<<<gg(NTOK, 256), 512, GEMM_SMEM>>>(ffn, l2w, l2b, t3, out,
                                               NTOK, 256, 1024, 256, 0, 0);
    ln_kernel<<<(NTOK * 32 + 255) / 256, 256>>>(out, n3g, n3b, NTOK);
}

// round 16
// speedup vs baseline: 1.1660x; 1.0584x over previous
#include <cuda_runtime.h>
#include <cuda_fp16.h>
#include <math.h>
#include <stdint.h>

// Problem constants (fixed by the reference)
#define NQ    900
#define BATCH 8
#define NTOK  (NQ*BATCH)        // 7200
#define DMODEL 256
#define HEADS 8
#define DFF   1024
#define S_TOT 19947
#define MTOK  (S_TOT*BATCH)     // 159576

// ---------------- scratch (static device arrays; no allocation) -------------
__device__ float g_qin[NTOK*DMODEL];
__device__ float g_cain[NTOK*DMODEL];
__device__ float g_qkv[NTOK*768];
__device__ float g_o  [NTOK*DMODEL];
__device__ float g_t2 [NTOK*DMODEL];
__device__ float g_off[NTOK*256];
__device__ float g_aw [NTOK*128];
__device__ float g_sx [NTOK*HEADS*16];
__device__ float g_sy [NTOK*HEADS*16];
__device__ float g_sw [NTOK*HEADS*16];
__device__ float g_val[(size_t)MTOK*DMODEL];
__device__ float g_ca [NTOK*DMODEL];
__device__ float g_t3 [NTOK*DMODEL];
__device__ float g_ffn[NTOK*DFF];

// ---------------- fast exp (FMA pipe, avoids MUFU bottleneck) ---------------
__device__ __forceinline__ float fexp(float x) {
    x = fmaxf(x, -80.f);
    float t  = x * 1.4426950408889634f;
    float fl = floorf(t);
    float f  = t - fl;
    float p  = 1.5403530e-4f;
    p = fmaf(p, f, 1.3333558e-3f);
    p = fmaf(p, f, 9.6181291e-3f);
    p = fmaf(p, f, 5.5504109e-2f);
    p = fmaf(p, f, 2.4022651e-1f);
    p = fmaf(p, f, 6.9314718e-1f);
    p = fmaf(p, f, 1.0f);
    int ei = (int)fl;
    float sc = __int_as_float((ei + 127) << 23);
    return p * sc;
}

// ---------------- fp16 pack helper -------------------------------------------
__device__ __forceinline__ uint32_t packh(float x, float y) {
    __half2 hb = __floats2half2_rn(x, y);
    return *(uint32_t*)&hb;
}

#define MMA_F16(d, a, b)                                                      \
  asm volatile("mma.sync.aligned.m16n8k16.row.col.f32.f16.f16.f32 "           \
      "{%0,%1,%2,%3}, {%4,%5,%6,%7}, {%8,%9}, {%0,%1,%2,%3};"                 \
      : "+f"(d[0]), "+f"(d[1]), "+f"(d[2]), "+f"(d[3])                        \
      : "r"(a[0]), "r"(a[1]), "r"(a[2]), "r"(a[3]), "r"(b[0]), "r"(b[1]))

#define LDSM4(R, addr)                                                        \
  asm volatile("ldmatrix.sync.aligned.m8n8.x4.shared.b16 {%0,%1,%2,%3}, [%4];"\
      : "=r"((R)[0]), "=r"((R)[1]), "=r"((R)[2]), "=r"((R)[3]) : "r"(addr))

// ---------------- tensor-core NT GEMM:  C[n,f] = A[n,:]·W[f,:] + bias -------
// A row-major [N,K]; W row-major [F,K]. F multiple of 128, K multiple of 32.
// Pure fp16 inputs, fp32 accumulate: statistical rel err ~1e-4 (< 1e-3 gate).
// BM=BN=128, BK=32 (two 16-wide sub-chunks, one barrier per 32-k),
// 512 threads, warp grid 4(m) x 4(n), warp tile 32x32.
// Dynamic smem: Ah/Bh x [2 buf][2 sub][128][12 words] = 49152 B.
#define GEMM_SMEM 49152
#define CHW 1536              // words per (buf,sub) chunk = 128*12
#define CHB 6144              // bytes per chunk
__global__ void __launch_bounds__(512, 1)
gemm_bf(const float* __restrict__ A, const float* __restrict__ W,
        const float* __restrict__ bias, const float* __restrict__ Res,
        float* __restrict__ C, int N, int F, int K, int ldc, int coff, int relu)
{
    extern __shared__ uint32_t dyn[];
    uint32_t* AhP = dyn;              // 4 chunks
    uint32_t* BhP = dyn + 4 * CHW;

    const int t    = threadIdx.x;
    const int row0 = blockIdx.y * 128, col0 = blockIdx.x * 128;
    const int lrow = t >> 2;            // 0..127 (loader row)
    const int lk   = (t & 3) << 2;      // float offset 0,4,8,12 within sub
    const int wid  = t >> 5, lane = t & 31;
    const int wm   = (wid >> 2) * 32;   // 0,32,64,96
    const int wn   = (wid & 3) * 32;    // 0,32,64,96
    const int g    = lane >> 2, c = lane & 3;

    // ldmatrix per-lane base addresses (chunk-relative)
    const uint32_t bAh = (uint32_t)__cvta_generic_to_shared(AhP);
    const uint32_t bBh = (uint32_t)__cvta_generic_to_shared(BhP);
    const int arow  = lane & 15;
    const int akoff = (lane >> 4) * 16;
    uint32_t aAh[2];
#pragma unroll
    for (int mi = 0; mi < 2; mi++) {
        uint32_t off = (uint32_t)((wm + mi * 16 + arow) * 48 + akoff);
        aAh[mi] = bAh + off;
    }
    const int brow  = (lane & 7) + ((lane >> 4) << 3);
    const int bkoff = ((lane >> 3) & 1) * 16;
    uint32_t aBh[2];
#pragma unroll
    for (int njp = 0; njp < 2; njp++) {
        uint32_t off = (uint32_t)((wn + njp * 16 + brow) * 48 + bkoff);
        aBh[njp] = bBh + off;
    }

    float acc[2][4][4];
#pragma unroll
    for (int mi = 0; mi < 2; mi++)
#pragma unroll
        for (int nj = 0; nj < 4; nj++)
#pragma unroll
            for (int e = 0; e < 4; e++) acc[mi][nj][e] = 0.f;

    const int nk = K >> 5;              // BK=32 iterations

    auto loadA = [&](int kg, int s, float4& u) {
        int gr = row0 + lrow;
        if (gr < N) u = *(const float4*)(A + (size_t)gr * K + kg + s * 16 + lk);
        else        u = make_float4(0.f, 0.f, 0.f, 0.f);
    };
    auto loadB = [&](int kg, int s, float4& u) {
        u = *(const float4*)(W + (size_t)(col0 + lrow) * K + kg + s * 16 + lk);
    };
    auto storeA = [&](int buf, int s, float4 u) {
        int co = (buf * 2 + s) * CHW + lrow * 12 + (t & 3) * 2;
        *(uint2*)&AhP[co] = make_uint2(packh(u.x, u.y), packh(u.z, u.w));
    };
    auto storeB = [&](int buf, int s, float4 u) {
        int co = (buf * 2 + s) * CHW + lrow * 12 + (t & 3) * 2;
        *(uint2*)&BhP[co] = make_uint2(packh(u.x, u.y), packh(u.z, u.w));
    };

    // --- prologue: k-chunk 0 (both subs) -> buffer 0 ---
    {
        float4 au, bu;
#pragma unroll
        for (int s = 0; s < 2; s++) {
            loadA(0, s, au);
            loadB(0, s, bu);
            storeA(0, s, au);
            storeB(0, s, bu);
        }
    }
    __syncthreads();

    for (int kt = 0; kt < nk; kt++) {
        const int buf = kt & 1;
        const bool pf = (kt + 1 < nk);
        float4 au[2], bu[2];
        if (pf) {
            int kg = (kt + 1) << 5;
#pragma unroll
            for (int s = 0; s < 2; s++) {
                loadA(kg, s, au[s]);
                loadB(kg, s, bu[s]);
            }
        }

#pragma unroll
        for (int s = 0; s < 2; s++) {
            const uint32_t co = (uint32_t)(buf * 2 + s) * CHB;
            uint32_t ah[2][4], bh[4][2];
#pragma unroll
            for (int mi = 0; mi < 2; mi++)
                LDSM4(ah[mi], aAh[mi] + co);
#pragma unroll
            for (int njp = 0; njp < 2; njp++) {
                uint32_t bt[4];
                LDSM4(bt, aBh[njp] + co);
                bh[njp*2  ][0] = bt[0];  bh[njp*2  ][1] = bt[1];
                bh[njp*2+1][0] = bt[2];  bh[njp*2+1][1] = bt[3];
            }
#pragma unroll
            for (int mi = 0; mi < 2; mi++)
#pragma unroll
                for (int nj = 0; nj < 4; nj++)
                    MMA_F16(acc[mi][nj], ah[mi], bh[nj]);
        }

        if (pf) {
            const int nb = buf ^ 1;
#pragma unroll
            for (int s = 0; s < 2; s++) {
                storeA(nb, s, au[s]);
                storeB(nb, s, bu[s]);
            }
        }
        __syncthreads();
    }

    // --- epilogue ---
#pragma unroll
    for (int mi = 0; mi < 2; mi++) {
#pragma unroll
        for (int h = 0; h < 2; h++) {
            int r = row0 + wm + mi * 16 + g + h * 8;
            if (r >= N) continue;
#pragma unroll
            for (int nj = 0; nj < 4; nj++) {
                int cc = col0 + wn + nj * 8 + c * 2;
                float v0 = acc[mi][nj][h * 2 + 0] + bias[cc];
                float v1 = acc[mi][nj][h * 2 + 1] + bias[cc + 1];
                if (Res) {
                    v0 += Res[(size_t)r * ldc + coff + cc];
                    v1 += Res[(size_t)r * ldc + coff + cc + 1];
                }
                if (relu) { v0 = fmaxf(v0, 0.f); v1 = fmaxf(v1, 0.f); }
                float* cp = C + (size_t)r * ldc + coff + cc;
                cp[0] = v0; cp[1] = v1;
            }
        }
    }
}

// ---------------- elementwise add (vectorized) -------------------------------
__global__ void add_kernel(const float4* __restrict__ a, const float4* __restrict__ b,
                           float4* __restrict__ o, int n4)
{
    int i = blockIdx.x * blockDim.x + threadIdx.x;
    if (i < n4) {
        float4 x = a[i], y = b[i];
        x.x += y.x; x.y += y.y; x.z += y.z; x.w += y.w;
        o[i] = x;
    }
}

// ---------------- flash self-attention, one query row / thread --------------
__global__ void __launch_bounds__(128)
attn_kernel(const float* __restrict__ qkv, float* __restrict__ o)
{
    const int bh = blockIdx.y;
    const int b = bh >> 3, h = bh & 7;
    const int qrow = blockIdx.x * 128 + threadIdx.x;
    const bool valid = qrow < NQ;

    float4 q[8];
    if (valid) {
        const float* qp = qkv + (size_t)(qrow * BATCH + b) * 768 + h * 32;
#pragma unroll
        for (int d = 0; d < 8; d++) {
            float4 v = *(const float4*)(qp + d * 4);
            const float s = 0.17677669529663687f;   // 1/sqrt(32)
            q[d].x = v.x * s; q[d].y = v.y * s; q[d].z = v.z * s; q[d].w = v.w * s;
        }
    }
    float4 acc[8];
#pragma unroll
    for (int d = 0; d < 8; d++) acc[d] = make_float4(0.f, 0.f, 0.f, 0.f);
    float mmax = -1e30f, lsum = 0.f;

    __shared__ float Ks[1024], Vs[1024];

    for (int m0 = 0; m0 < NQ; m0 += 32) {
        int nrows = min(32, NQ - m0);
        {
            int fi = threadIdx.x * 8;
            int r = fi >> 5, d0 = fi & 31;
            if (r < nrows) {
                const float* kp = qkv + (size_t)((m0 + r) * BATCH + b) * 768 + 256 + h * 32 + d0;
                *(float4*)(Ks + fi)     = *(const float4*)kp;
                *(float4*)(Ks + fi + 4) = *(const float4*)(kp + 4);
                const float* vp = kp + 256;
                *(float4*)(Vs + fi)     = *(const float4*)vp;
                *(float4*)(Vs + fi + 4) = *(const float4*)(vp + 4);
            }
        }
        __syncthreads();

        if (valid) {
            float s[32];
            float tmax = -1e30f;
            for (int j = 0; j < nrows; j++) {
                const float4* kr = (const float4*)(Ks + j * 32);
                float d0 = 0.f, d1 = 0.f, d2 = 0.f, d3 = 0.f;
#pragma unroll
                for (int d = 0; d < 8; d++) {
                    float4 kv = kr[d];
                    d0 = fmaf(q[d].x, kv.x, d0);
                    d1 = fmaf(q[d].y, kv.y, d1);
                    d2 = fmaf(q[d].z, kv.z, d2);
                    d3 = fmaf(q[d].w, kv.w, d3);
                }
                s[j] = (d0 + d1) + (d2 + d3);
                tmax = fmaxf(tmax, s[j]);
            }
            float mnew = fmaxf(mmax, tmax);
            float corr = fexp(mmax - mnew);
            lsum *= corr;
#pragma unroll
            for (int d = 0; d < 8; d++) {
                acc[d].x *= corr; acc[d].y *= corr; acc[d].z *= corr; acc[d].w *= corr;
            }
            for (int j = 0; j < nrows; j++) {
                float p = fexp(s[j] - mnew);
                lsum += p;
                const float4* vr = (const float4*)(Vs + j * 32);
#pragma unroll
                for (int d = 0; d < 8; d++) {
                    float4 vv = vr[d];
                    acc[d].x = fmaf(p, vv.x, acc[d].x);
                    acc[d].y = fmaf(p, vv.y, acc[d].y);
                    acc[d].z = fmaf(p, vv.z, acc[d].z);
                    acc[d].w = fmaf(p, vv.w, acc[d].w);
                }
            }
            mmax = mnew;
        }
        __syncthreads();
    }

    if (valid) {
        float inv = 1.f / lsum;
        float* op = o + (size_t)(qrow * BATCH + b) * DMODEL + h * 32;
#pragma unroll
        for (int d = 0; d < 8; d++) {
            float4 v;
            v.x = acc[d].x * inv; v.y = acc[d].y * inv;
            v.z = acc[d].z * inv; v.w = acc[d].w * inv;
            *(float4*)(op + d * 4) = v;
        }
    }
}

// ---------------- LayerNorm, in-place, warp per row (256 cols) --------------
__global__ void ln_kernel(float* __restrict__ x, const float* __restrict__ g,
                          const float* __restrict__ bt, int rows)
{
    int gid = blockIdx.x * blockDim.x + threadIdx.x;
    int r = gid >> 5;
    if (r >= rows) return;
    int lane = gid & 31;
    float* row = x + (size_t)r * 256;
    float v[8]; float s = 0.f;
#pragma unroll
    for (int i = 0; i < 8; i++) { v[i] = row[lane + i * 32]; s += v[i]; }
#pragma unroll
    for (int o = 16; o > 0; o >>= 1) s += __shfl_xor_sync(0xffffffffu, s, o);
    float mean = s * (1.f / 256.f);
    float vs = 0.f;
#pragma unroll
    for (int i = 0; i < 8; i++) { float d = v[i] - mean; vs = fmaf(d, d, vs); }
#pragma unroll
    for (int o = 16; o > 0; o >>= 1) vs += __shfl_xor_sync(0xffffffffu, vs, o);
    float rst = rsqrtf(vs * (1.f / 256.f) + 1e-5f);
#pragma unroll
    for (int i = 0; i < 8; i++) {
        int c = lane + i * 32;
        row[c] = (v[i] - mean) * rst * g[c] + bt[c];
    }
}

// ---------------- deform-attn sampling precompute ---------------------------
__global__ void prep_kernel(const float* __restrict__ off, const float* __restrict__ aw,
                            const float* __restrict__ ref,
                            float* __restrict__ sx, float* __restrict__ sy,
                            float* __restrict__ sw)
{
    int idx = blockIdx.x * blockDim.x + threadIdx.x;
    if (idx >= NTOK * HEADS) return;
    int n = idx >> 3, h = idx & 7;
    const float* op = off + (size_t)n * 256 + h * 32;
    const float* ap = aw  + (size_t)n * 128 + h * 16;
    const float* rp = ref + (size_t)n * 16;

    float a[16]; float mx = -1e30f;
#pragma unroll
    for (int t = 0; t < 16; t++) { a[t] = ap[t]; mx = fmaxf(mx, a[t]); }
    float ssum = 0.f;
#pragma unroll
    for (int t = 0; t < 16; t++) { a[t] = fexp(a[t] - mx); ssum += a[t]; }
    float inv = 1.f / ssum;

    const float Wd[4] = {150.f, 75.f, 38.f, 19.f};
    const float Hh[4] = {100.f, 50.f, 25.f, 13.f};
#pragma unroll
    for (int l = 0; l < 4; l++) {
        float cx = rp[l*4+0], cy = rp[l*4+1], rw = rp[l*4+2], rh = rp[l*4+3];
#pragma unroll
        for (int p = 0; p < 4; p++) {
            float ox = op[(l*4+p)*2+0], oy = op[(l*4+p)*2+1];
            float lx = fmaf(ox * 0.25f * 0.5f, rw, cx);
            float ly = fmaf(oy * 0.25f * 0.5f, rh, cy);
            int o_ = idx * 16 + l * 4 + p;
            sx[o_] = lx * Wd[l] - 0.5f;
            sy[o_] = ly * Hh[l] - 0.5f;
            sw[o_] = a[l*4+p] * inv;
        }
    }
}

// ---------------- deform-attn gather: warp per (token, head), lane = dh -----
__global__ void gather_kernel(const float* __restrict__ val,
                              const float* __restrict__ sx, const float* __restrict__ sy,
                              const float* __restrict__ sw, float* __restrict__ ca)
{
    int gtid = blockIdx.x * blockDim.x + threadIdx.x;
    int wid = gtid >> 5;
    if (wid >= NTOK * HEADS) return;
    int lane = gtid & 31;
    int n = wid >> 3, h = wid & 7;
    int b = n & 7;

    const int cW[4] = {150, 75, 38, 19};
    const int cH[4] = {100, 50, 25, 13};
    const int cS[4] = {0, 15000, 18750, 19700};

    const float* vbase = val + (size_t)b * 256 + h * 32 + lane;
    float acc = 0.f;
#pragma unroll
    for (int t = 0; t < 16; t++) {
        int l = t >> 2;
        float x = sx[wid * 16 + t];
        float y = sy[wid * 16 + t];
        float w = sw[wid * 16 + t];
        float xf = floorf(x), yf = floorf(y);
        int x0 = (int)xf, y0 = (int)yf;
        float fx = x - xf, fy = y - yf;
        int W_ = cW[l], H_ = cH[l];
#pragma unroll
        for (int dy = 0; dy < 2; dy++) {
            int yi = y0 + dy;
            if (yi < 0 || yi >= H_) continue;
            float wy = dy ? fy : (1.f - fy);
#pragma unroll
            for (int dx = 0; dx < 2; dx++) {
                int xi = x0 + dx;
                if (xi < 0 || xi >= W_) continue;
                float wx = dx ? fx : (1.f - fx);
                int s = cS[l] + yi * W_ + xi;
                acc = fmaf(w * wy * wx, __ldg(vbase + (size_t)s * (BATCH * 256)), acc);
            }
        }
    }
    ca[(size_t)n * 256 + h * 32 + lane] = acc;
}

// ---------------- launch ----------------------------------------------------
extern "C" void kernel_launch(void* const* d_in, const int* in_sizes, int n_in,
                              void* d_out, int out_size)
{
    (void)in_sizes; (void)n_in; (void)out_size;
    const float* tgt   = (const float*)d_in[0];
    const float* pos   = (const float*)d_in[1];
    const float* ref   = (const float*)d_in[2];
    const float* mem   = (const float*)d_in[3];
    const float* in_w  = (const float*)d_in[6];
    const float* in_b  = (const float*)d_in[7];
    const float* sow   = (const float*)d_in[8];
    const float* sob   = (const float*)d_in[9];
    const float* n1g   = (const float*)d_in[10];
    const float* n1b   = (const float*)d_in[11];
    const float* n2g   = (const float*)d_in[12];
    const float* n2b   = (const float*)d_in[13];
    const float* n3g   = (const float*)d_in[14];
    const float* n3b   = (const float*)d_in[15];
    const float* off_w = (const float*)d_in[16];
    const float* off_b = (const float*)d_in[17];
    const float* aw_w  = (const float*)d_in[18];
    const float* aw_b  = (const float*)d_in[19];
    const float* val_w = (const float*)d_in[20];
    const float* val_b = (const float*)d_in[21];
    const float* cow   = (const float*)d_in[22];
    const float* cob   = (const float*)d_in[23];
    const float* l1w   = (const float*)d_in[24];
    const float* l1b   = (const float*)d_in[25];
    const float* l2w   = (const float*)d_in[26];
    const float* l2b   = (const float*)d_in[27];
    float* out = (float*)d_out;

    float *qin, *cain, *qkv, *o_, *t2, *offb, *awb, *sx, *sy, *sw, *val, *ca, *t3, *ffn;
    cudaGetSymbolAddress((void**)&qin,  g_qin);
    cudaGetSymbolAddress((void**)&cain, g_cain);
    cudaGetSymbolAddress((void**)&qkv,  g_qkv);
    cudaGetSymbolAddress((void**)&o_,   g_o);
    cudaGetSymbolAddress((void**)&t2,   g_t2);
    cudaGetSymbolAddress((void**)&offb, g_off);
    cudaGetSymbolAddress((void**)&awb,  g_aw);
    cudaGetSymbolAddress((void**)&sx,   g_sx);
    cudaGetSymbolAddress((void**)&sy,   g_sy);
    cudaGetSymbolAddress((void**)&sw,   g_sw);
    cudaGetSymbolAddress((void**)&val,  g_val);
    cudaGetSymbolAddress((void**)&ca,   g_ca);
    cudaGetSymbolAddress((void**)&t3,   g_t3);
    cudaGetSymbolAddress((void**)&ffn,  g_ffn);

    // one-time stream/event/attr setup (first, non-captured call)
    static cudaStream_t s2 = nullptr;
    static cudaEvent_t ev_fork = nullptr, ev_join = nullptr;
    if (!s2) {
        cudaStreamCreateWithFlags(&s2, cudaStreamNonBlocking);
        cudaEventCreateWithFlags(&ev_fork, cudaEventDisableTiming);
        cudaEventCreateWithFlags(&ev_join, cudaEventDisableTiming);
        cudaFuncSetAttribute(gemm_bf, cudaFuncAttributeMaxDynamicSharedMemorySize,
                             GEMM_SMEM);
    }

    auto gg = [](int N, int F) { return dim3((unsigned)(F / 128), (unsigned)((N + 127) / 128)); };
    const int n4 = NTOK * DMODEL / 4;

    // ---- fork: val projection GEMM runs concurrently on s2 ----
    cudaEventRecord(ev_fork, 0);
    cudaStreamWaitEvent(s2, ev_fork, 0);
    gemm_bf<<<gg(MTOK, 256), 512, GEMM_SMEM, s2>>>(mem, val_w, val_b, nullptr, val,
                                                   MTOK, 256, 256, 256, 0, 0);
    cudaEventRecord(ev_join, s2);

    // ---- main chain on the capture stream ----
    // 1) qin = tgt + pos
    add_kernel<<<(n4 + 255) / 256, 256>>>((const float4*)tgt, (const float4*)pos,
                                          (float4*)qin, n4);
    // 2-3) QKV projection: q,k from qin; v from tgt
    gemm_bf<<<gg(NTOK, 512), 512, GEMM_SMEM>>>(qin, in_w, in_b, nullptr, qkv,
                                               NTOK, 512, 256, 768, 0, 0);
    gemm_bf<<<gg(NTOK, 256), 512, GEMM_SMEM>>>(tgt, in_w + 512 * 256, in_b + 512, nullptr, qkv,
                                               NTOK, 256, 256, 768, 512, 0);
    // 4) self attention
    attn_kernel<<<dim3((NQ + 127) / 128, BATCH * HEADS), 128>>>(qkv, o_);
    // 5) out proj + residual(tgt), then LN2 -> t2
    gemm_bf<<<gg(NTOK, 256), 512, GEMM_SMEM>>>(o_, sow, sob, tgt, t2,
                                               NTOK, 256, 256, 256, 0, 0);
    ln_kernel<<<(NTOK * 32 + 255) / 256, 256>>>(t2, n2g, n2b, NTOK);
    // 6) cain = t2 + pos
    add_kernel<<<(n4 + 255) / 256, 256>>>((const float4*)t2, (const float4*)pos,
                                          (float4*)cain, n4);
    // 7-8) sampling offsets + attention weights from cain
    gemm_bf<<<gg(NTOK, 256), 512, GEMM_SMEM>>>(cain, off_w, off_b, nullptr, offb,
                                               NTOK, 256, 256, 256, 0, 0);
    gemm_bf<<<gg(NTOK, 128), 512, GEMM_SMEM>>>(cain, aw_w, aw_b, nullptr, awb,
                                               NTOK, 128, 256, 128, 0, 0);
    // 9) softmax + sample coords
    prep_kernel<<<(NTOK * HEADS + 255) / 256, 256>>>(offb, awb, ref, sx, sy, sw);

    // ---- join: gather needs the val projection ----
    cudaStreamWaitEvent(0, ev_join, 0);

    // 10) bilinear gather
    gather_kernel<<<(NTOK * HEADS * 32 + 255) / 256, 256>>>(val, sx, sy, sw, ca);
    // 11) ca out proj + residual(t2), LN1 -> t3
    gemm_bf<<<gg(NTOK, 256), 512, GEMM_SMEM>>>(ca, cow, cob, t2, t3,
                                               NTOK, 256, 256, 256, 0, 0);
    ln_kernel<<<(NTOK * 32 + 255) / 256, 256>>>(t3, n1g, n1b, NTOK);
    // 12) FFN
    gemm_bf<<<gg(NTOK, 1024), 512, GEMM_SMEM>>>(t3, l1w, l1b, nullptr, ffn,
                                                NTOK, 1024, 256, 1024, 0, 1);
    gemm_bf<<<gg(NTOK, 256), 512, GEMM_SMEM>>>(ffn, l2w, l2b, t3, out,
                                               NTOK, 256, 1024, 256, 0, 0);
    ln_kernel<<<(NTOK * 32 + 255) / 256, 256>>>(out, n3g, n3b, NTOK);
}

// round 17
// speedup vs baseline: 1.1953x; 1.0251x over previous
#include <cuda_runtime.h>
#include <cuda_fp16.h>
#include <math.h>
#include <stdint.h>

// Problem constants (fixed by the reference)
#define NQ    900
#define BATCH 8
#define NTOK  (NQ*BATCH)        // 7200
#define DMODEL 256
#define HEADS 8
#define DFF   1024
#define S_TOT 19947
#define MTOK  (S_TOT*BATCH)     // 159576

// ---------------- scratch (static device arrays; no allocation) -------------
__device__ float g_qkv[NTOK*768];
__device__ float g_t2 [NTOK*DMODEL];
__device__ float g_off[NTOK*256];
__device__ float g_aw [NTOK*128];
__device__ float g_sx [NTOK*HEADS*16];
__device__ float g_sy [NTOK*HEADS*16];
__device__ float g_sw [NTOK*HEADS*16];
__device__ float g_val[(size_t)MTOK*DMODEL];
__device__ float g_t3 [NTOK*DMODEL];

// fp16 operand buffers
#define HW_INW  0
#define HW_SOW  196608
#define HW_OFFW 262144
#define HW_AWW  327680
#define HW_VALW 360448
#define HW_COW  425984
#define HW_L1W  491520
#define HW_L2W  753664
__device__ __half h_wts[1015808];
__device__ __half h_mem[(size_t)MTOK*256];
__device__ __half h_qin[NTOK*256];
__device__ __half h_tgt[NTOK*256];
__device__ __half h_o  [NTOK*256];
__device__ __half h_cain[NTOK*256];
__device__ __half h_ca [NTOK*256];
__device__ __half h_t3 [NTOK*256];
__device__ __half h_ffn[NTOK*1024];

// ---------------- fast exp (FMA pipe, avoids MUFU bottleneck) ---------------
__device__ __forceinline__ float fexp(float x) {
    x = fmaxf(x, -80.f);
    float t  = x * 1.4426950408889634f;
    float fl = floorf(t);
    float f  = t - fl;
    float p  = 1.5403530e-4f;
    p = fmaf(p, f, 1.3333558e-3f);
    p = fmaf(p, f, 9.6181291e-3f);
    p = fmaf(p, f, 5.5504109e-2f);
    p = fmaf(p, f, 2.4022651e-1f);
    p = fmaf(p, f, 6.9314718e-1f);
    p = fmaf(p, f, 1.0f);
    int ei = (int)fl;
    float sc = __int_as_float((ei + 127) << 23);
    return p * sc;
}

#define MMA_F16(d, a, b)                                                      \
  asm volatile("mma.sync.aligned.m16n8k16.row.col.f32.f16.f16.f32 "           \
      "{%0,%1,%2,%3}, {%4,%5,%6,%7}, {%8,%9}, {%0,%1,%2,%3};"                 \
      : "+f"(d[0]), "+f"(d[1]), "+f"(d[2]), "+f"(d[3])                        \
      : "r"(a[0]), "r"(a[1]), "r"(a[2]), "r"(a[3]), "r"(b[0]), "r"(b[1]))

#define LDSM4(R, addr)                                                        \
  asm volatile("ldmatrix.sync.aligned.m8n8.x4.shared.b16 {%0,%1,%2,%3}, [%4];"\
      : "=r"((R)[0]), "=r"((R)[1]), "=r"((R)[2]), "=r"((R)[3]) : "r"(addr))

#define CP16(dst, src, sz)                                                    \
  asm volatile("cp.async.cg.shared.global [%0], [%1], 16, %2;"                \
      :: "r"(dst), "l"(src), "r"(sz))
#define CP_COMMIT() asm volatile("cp.async.commit_group;" ::: "memory")
#define CP_WAIT1()  asm volatile("cp.async.wait_group 1;" ::: "memory")

// ---------------- tensor-core NT GEMM (fp16 in, fp32 acc) -------------------
// A fp16 row-major [N,K]; W fp16 row-major [F,K]. F mult 128, K mult 32.
// BM=BN=128, BK=32 (two 16-k sub-chunks), 512 threads, 3-stage cp.async ring.
// Stage layout (24576 B): A sub0 | A sub1 | B sub0 | B sub1 (6144 B each,
// row stride 48 B -> conflict-free ldmatrix).
#define GEMM_SMEM 73728
__global__ void __launch_bounds__(512, 1)
gemm_h(const __half* __restrict__ A, const __half* __restrict__ W,
       const float* __restrict__ bias, const float* __restrict__ Res,
       float* __restrict__ C, __half* __restrict__ Ch,
       int N, int F, int K, int ldc, int coff, int relu)
{
    extern __shared__ uint32_t dyn[];
    const uint32_t sbase = (uint32_t)__cvta_generic_to_shared(dyn);

    const int t = threadIdx.x;
    const int row0 = blockIdx.y * 128, col0 = blockIdx.x * 128;
    const int wid = t >> 5, lane = t & 31;
    const int wm = (wid >> 2) * 32, wn = (wid & 3) * 32;
    const int g = lane >> 2, c = lane & 3;

    // loader mapping: each thread moves one 16B A-chunk + one 16B B-chunk/iter
    const int subL  = t >> 8;           // 0..1
    const int rowL  = (t & 255) >> 1;   // 0..127
    const int halfL = t & 1;            // 0..1
    const int grA   = row0 + rowL;
    const __half* srcA0 = A + (size_t)grA * K + subL * 16 + halfL * 8;
    const __half* srcB0 = W + (size_t)(col0 + rowL) * K + subL * 16 + halfL * 8;
    const uint32_t dstA0 = sbase + (uint32_t)(subL * 6144 + rowL * 48 + halfL * 16);
    const uint32_t szA = (grA < N) ? 16u : 0u;

    // fragment base addresses (stage-relative)
    const int arow  = lane & 15;
    const int akoff = (lane >> 4) * 16;
    uint32_t aA[2];
#pragma unroll
    for (int mi = 0; mi < 2; mi++)
        aA[mi] = sbase + (uint32_t)((wm + mi * 16 + arow) * 48 + akoff);
    const int brow  = (lane & 7) + ((lane >> 4) << 3);
    const int bkoff = ((lane >> 3) & 1) * 16;
    uint32_t aB[2];
#pragma unroll
    for (int njp = 0; njp < 2; njp++)
        aB[njp] = sbase + 12288u + (uint32_t)((wn + njp * 16 + brow) * 48 + bkoff);

    float acc[2][4][4];
#pragma unroll
    for (int mi = 0; mi < 2; mi++)
#pragma unroll
        for (int nj = 0; nj < 4; nj++)
#pragma unroll
            for (int e = 0; e < 4; e++) acc[mi][nj][e] = 0.f;

    const int nk = K >> 5;

    auto issue = [&](int kt) {
        const uint32_t so = (uint32_t)(kt % 3) * 24576u;
        const int kg = kt << 5;
        CP16(dstA0 + so, srcA0 + kg, szA);
        CP16(dstA0 + 12288u + so, srcB0 + kg, 16u);
    };

    issue(0); CP_COMMIT();
    if (nk > 1) issue(1);
    CP_COMMIT();

    for (int kt = 0; kt < nk; kt++) {
        CP_WAIT1();
        __syncthreads();

        const uint32_t so = (uint32_t)(kt % 3) * 24576u;
#pragma unroll
        for (int s = 0; s < 2; s++) {
            const uint32_t co = so + (uint32_t)s * 6144u;
            uint32_t ah[2][4], bh[4][2];
#pragma unroll
            for (int mi = 0; mi < 2; mi++)
                LDSM4(ah[mi], aA[mi] + co);
#pragma unroll
            for (int njp = 0; njp < 2; njp++) {
                uint32_t bt[4];
                LDSM4(bt, aB[njp] + co);
                bh[njp*2  ][0] = bt[0];  bh[njp*2  ][1] = bt[1];
                bh[njp*2+1][0] = bt[2];  bh[njp*2+1][1] = bt[3];
            }
#pragma unroll
            for (int mi = 0; mi < 2; mi++)
#pragma unroll
                for (int nj = 0; nj < 4; nj++)
                    MMA_F16(acc[mi][nj], ah[mi], bh[nj]);
        }

        if (kt + 2 < nk) issue(kt + 2);
        CP_COMMIT();
    }

    // --- epilogue ---
#pragma unroll
    for (int mi = 0; mi < 2; mi++) {
#pragma unroll
        for (int h = 0; h < 2; h++) {
            int r = row0 + wm + mi * 16 + g + h * 8;
            if (r >= N) continue;
#pragma unroll
            for (int nj = 0; nj < 4; nj++) {
                int cc = col0 + wn + nj * 8 + c * 2;
                float v0 = acc[mi][nj][h * 2 + 0] + bias[cc];
                float v1 = acc[mi][nj][h * 2 + 1] + bias[cc + 1];
                if (Res) {
                    v0 += Res[(size_t)r * ldc + coff + cc];
                    v1 += Res[(size_t)r * ldc + coff + cc + 1];
                }
                if (relu) { v0 = fmaxf(v0, 0.f); v1 = fmaxf(v1, 0.f); }
                if (C) {
                    float* cp = C + (size_t)r * ldc + coff + cc;
                    cp[0] = v0; cp[1] = v1;
                }
                if (Ch) {
                    *(__half2*)(Ch + (size_t)r * ldc + coff + cc) =
                        __floats2half2_rn(v0, v1);
                }
            }
        }
    }
}

// ---------------- conversion kernels -----------------------------------------
__global__ void cvt_kernel(const float4* __restrict__ s, __half2* __restrict__ d,
                           int n4)
{
    int i = blockIdx.x * blockDim.x + threadIdx.x;
    if (i < n4) {
        float4 v = s[i];
        d[i * 2]     = __floats2half2_rn(v.x, v.y);
        d[i * 2 + 1] = __floats2half2_rn(v.z, v.w);
    }
}

// fused weight conversion: 8 segments -> h_wts (contiguous, segment order)
__global__ void cvt_wts(const float4* s0, const float4* s1, const float4* s2,
                        const float4* s3, const float4* s4, const float4* s5,
                        const float4* s6, const float4* s7, __half2* dst)
{
    int i = blockIdx.x * blockDim.x + threadIdx.x;
    if (i >= 253952) return;
    const float4* s; int base;
    if      (i <  49152) { s = s0; base = 0; }
    else if (i <  65536) { s = s1; base = 49152; }
    else if (i <  81920) { s = s2; base = 65536; }
    else if (i <  90112) { s = s3; base = 81920; }
    else if (i < 106496) { s = s4; base = 90112; }
    else if (i < 122880) { s = s5; base = 106496; }
    else if (i < 188416) { s = s6; base = 122880; }
    else                 { s = s7; base = 188416; }
    float4 v = s[i - base];
    dst[i * 2]     = __floats2half2_rn(v.x, v.y);
    dst[i * 2 + 1] = __floats2half2_rn(v.z, v.w);
}

// ---------------- elementwise add -> fp16 ------------------------------------
__global__ void add_kernel(const float4* __restrict__ a, const float4* __restrict__ b,
                           __half2* __restrict__ o, int n4)
{
    int i = blockIdx.x * blockDim.x + threadIdx.x;
    if (i < n4) {
        float4 x = a[i], y = b[i];
        o[i * 2]     = __floats2half2_rn(x.x + y.x, x.y + y.y);
        o[i * 2 + 1] = __floats2half2_rn(x.z + y.z, x.w + y.w);
    }
}

// ---------------- flash self-attention, one query row / thread --------------
__global__ void __launch_bounds__(128)
attn_kernel(const float* __restrict__ qkv, __half* __restrict__ oh)
{
    const int bh = blockIdx.y;
    const int b = bh >> 3, h = bh & 7;
    const int qrow = blockIdx.x * 128 + threadIdx.x;
    const bool valid = qrow < NQ;

    float4 q[8];
    if (valid) {
        const float* qp = qkv + (size_t)(qrow * BATCH + b) * 768 + h * 32;
#pragma unroll
        for (int d = 0; d < 8; d++) {
            float4 v = *(const float4*)(qp + d * 4);
            const float s = 0.17677669529663687f;   // 1/sqrt(32)
            q[d].x = v.x * s; q[d].y = v.y * s; q[d].z = v.z * s; q[d].w = v.w * s;
        }
    }
    float4 acc[8];
#pragma unroll
    for (int d = 0; d < 8; d++) acc[d] = make_float4(0.f, 0.f, 0.f, 0.f);
    float mmax = -1e30f, lsum = 0.f;

    __shared__ float Ks[1024], Vs[1024];

    for (int m0 = 0; m0 < NQ; m0 += 32) {
        int nrows = min(32, NQ - m0);
        {
            int fi = threadIdx.x * 8;
            int r = fi >> 5, d0 = fi & 31;
            if (r < nrows) {
                const float* kp = qkv + (size_t)((m0 + r) * BATCH + b) * 768 + 256 + h * 32 + d0;
                *(float4*)(Ks + fi)     = *(const float4*)kp;
                *(float4*)(Ks + fi + 4) = *(const float4*)(kp + 4);
                const float* vp = kp + 256;
                *(float4*)(Vs + fi)     = *(const float4*)vp;
                *(float4*)(Vs + fi + 4) = *(const float4*)(vp + 4);
            }
        }
        __syncthreads();

        if (valid) {
            float s[32];
            float tmax = -1e30f;
            for (int j = 0; j < nrows; j++) {
                const float4* kr = (const float4*)(Ks + j * 32);
                float d0 = 0.f, d1 = 0.f, d2 = 0.f, d3 = 0.f;
#pragma unroll
                for (int d = 0; d < 8; d++) {
                    float4 kv = kr[d];
                    d0 = fmaf(q[d].x, kv.x, d0);
                    d1 = fmaf(q[d].y, kv.y, d1);
                    d2 = fmaf(q[d].z, kv.z, d2);
                    d3 = fmaf(q[d].w, kv.w, d3);
                }
                s[j] = (d0 + d1) + (d2 + d3);
                tmax = fmaxf(tmax, s[j]);
            }
            float mnew = fmaxf(mmax, tmax);
            float corr = fexp(mmax - mnew);
            lsum *= corr;
#pragma unroll
            for (int d = 0; d < 8; d++) {
                acc[d].x *= corr; acc[d].y *= corr; acc[d].z *= corr; acc[d].w *= corr;
            }
            for (int j = 0; j < nrows; j++) {
                float p = fexp(s[j] - mnew);
                lsum += p;
                const float4* vr = (const float4*)(Vs + j * 32);
#pragma unroll
                for (int d = 0; d < 8; d++) {
                    float4 vv = vr[d];
                    acc[d].x = fmaf(p, vv.x, acc[d].x);
                    acc[d].y = fmaf(p, vv.y, acc[d].y);
                    acc[d].z = fmaf(p, vv.z, acc[d].z);
                    acc[d].w = fmaf(p, vv.w, acc[d].w);
                }
            }
            mmax = mnew;
        }
        __syncthreads();
    }

    if (valid) {
        float inv = 1.f / lsum;
        __half2* op = (__half2*)(oh + (size_t)(qrow * BATCH + b) * DMODEL + h * 32);
#pragma unroll
        for (int d = 0; d < 8; d++) {
            op[d * 2]     = __floats2half2_rn(acc[d].x * inv, acc[d].y * inv);
            op[d * 2 + 1] = __floats2half2_rn(acc[d].z * inv, acc[d].w * inv);
        }
    }
}

// ---------------- LayerNorm, in-place, warp per row; optional fp16 copy -----
__global__ void ln_kernel(float* __restrict__ x, const float* __restrict__ g,
                          const float* __restrict__ bt, int rows,
                          __half* __restrict__ xh)
{
    int gid = blockIdx.x * blockDim.x + threadIdx.x;
    int r = gid >> 5;
    if (r >= rows) return;
    int lane = gid & 31;
    float* row = x + (size_t)r * 256;
    float v[8]; float s = 0.f;
#pragma unroll
    for (int i = 0; i < 8; i++) { v[i] = row[lane + i * 32]; s += v[i]; }
#pragma unroll
    for (int o = 16; o > 0; o >>= 1) s += __shfl_xor_sync(0xffffffffu, s, o);
    float mean = s * (1.f / 256.f);
    float vs = 0.f;
#pragma unroll
    for (int i = 0; i < 8; i++) { float d = v[i] - mean; vs = fmaf(d, d, vs); }
#pragma unroll
    for (int o = 16; o > 0; o >>= 1) vs += __shfl_xor_sync(0xffffffffu, vs, o);
    float rst = rsqrtf(vs * (1.f / 256.f) + 1e-5f);
#pragma unroll
    for (int i = 0; i < 8; i++) {
        int c = lane + i * 32;
        float o = (v[i] - mean) * rst * g[c] + bt[c];
        row[c] = o;
        if (xh) xh[(size_t)r * 256 + c] = __float2half(o);
    }
}

// ---------------- deform-attn sampling precompute ---------------------------
__global__ void prep_kernel(const float* __restrict__ off, const float* __restrict__ aw,
                            const float* __restrict__ ref,
                            float* __restrict__ sx, float* __restrict__ sy,
                            float* __restrict__ sw)
{
    int idx = blockIdx.x * blockDim.x + threadIdx.x;
    if (idx >= NTOK * HEADS) return;
    int n = idx >> 3, h = idx & 7;
    const float* op = off + (size_t)n * 256 + h * 32;
    const float* ap = aw  + (size_t)n * 128 + h * 16;
    const float* rp = ref + (size_t)n * 16;

    float a[16]; float mx = -1e30f;
#pragma unroll
    for (int t = 0; t < 16; t++) { a[t] = ap[t]; mx = fmaxf(mx, a[t]); }
    float ssum = 0.f;
#pragma unroll
    for (int t = 0; t < 16; t++) { a[t] = fexp(a[t] - mx); ssum += a[t]; }
    float inv = 1.f / ssum;

    const float Wd[4] = {150.f, 75.f, 38.f, 19.f};
    const float Hh[4] = {100.f, 50.f, 25.f, 13.f};
#pragma unroll
    for (int l = 0; l < 4; l++) {
        float cx = rp[l*4+0], cy = rp[l*4+1], rw = rp[l*4+2], rh = rp[l*4+3];
#pragma unroll
        for (int p = 0; p < 4; p++) {
            float ox = op[(l*4+p)*2+0], oy = op[(l*4+p)*2+1];
            float lx = fmaf(ox * 0.25f * 0.5f, rw, cx);
            float ly = fmaf(oy * 0.25f * 0.5f, rh, cy);
            int o_ = idx * 16 + l * 4 + p;
            sx[o_] = lx * Wd[l] - 0.5f;
            sy[o_] = ly * Hh[l] - 0.5f;
            sw[o_] = a[l*4+p] * inv;
        }
    }
}

// ---------------- deform-attn gather: warp per (token, head) -> fp16 --------
__global__ void gather_kernel(const float* __restrict__ val,
                              const float* __restrict__ sx, const float* __restrict__ sy,
                              const float* __restrict__ sw, __half* __restrict__ cah)
{
    int gtid = blockIdx.x * blockDim.x + threadIdx.x;
    int wid = gtid >> 5;
    if (wid >= NTOK * HEADS) return;
    int lane = gtid & 31;
    int n = wid >> 3, h = wid & 7;
    int b = n & 7;

    const int cW[4] = {150, 75, 38, 19};
    const int cH[4] = {100, 50, 25, 13};
    const int cS[4] = {0, 15000, 18750, 19700};

    const float* vbase = val + (size_t)b * 256 + h * 32 + lane;
    float acc = 0.f;
#pragma unroll
    for (int t = 0; t < 16; t++) {
        int l = t >> 2;
        float x = sx[wid * 16 + t];
        float y = sy[wid * 16 + t];
        float w = sw[wid * 16 + t];
        float xf = floorf(x), yf = floorf(y);
        int x0 = (int)xf, y0 = (int)yf;
        float fx = x - xf, fy = y - yf;
        int W_ = cW[l], H_ = cH[l];
#pragma unroll
        for (int dy = 0; dy < 2; dy++) {
            int yi = y0 + dy;
            if (yi < 0 || yi >= H_) continue;
            float wy = dy ? fy : (1.f - fy);
#pragma unroll
            for (int dx = 0; dx < 2; dx++) {
                int xi = x0 + dx;
                if (xi < 0 || xi >= W_) continue;
                float wx = dx ? fx : (1.f - fx);
                int s = cS[l] + yi * W_ + xi;
                acc = fmaf(w * wy * wx, __ldg(vbase + (size_t)s * (BATCH * 256)), acc);
            }
        }
    }
    cah[(size_t)n * 256 + h * 32 + lane] = __float2half(acc);
}

// ---------------- launch ----------------------------------------------------
extern "C" void kernel_launch(void* const* d_in, const int* in_sizes, int n_in,
                              void* d_out, int out_size)
{
    (void)in_sizes; (void)n_in; (void)out_size;
    const float* tgt   = (const float*)d_in[0];
    const float* pos   = (const float*)d_in[1];
    const float* ref   = (const float*)d_in[2];
    const float* mem   = (const float*)d_in[3];
    const float* in_w  = (const float*)d_in[6];
    const float* in_b  = (const float*)d_in[7];
    const float* sow   = (const float*)d_in[8];
    const float* sob   = (const float*)d_in[9];
    const float* n1g   = (const float*)d_in[10];
    const float* n1b   = (const float*)d_in[11];
    const float* n2g   = (const float*)d_in[12];
    const float* n2b   = (const float*)d_in[13];
    const float* n3g   = (const float*)d_in[14];
    const float* n3b   = (const float*)d_in[15];
    const float* off_w = (const float*)d_in[16];
    const float* off_b = (const float*)d_in[17];
    const float* aw_w  = (const float*)d_in[18];
    const float* aw_b  = (const float*)d_in[19];
    const float* val_w = (const float*)d_in[20];
    const float* val_b = (const float*)d_in[21];
    const float* cow   = (const float*)d_in[22];
    const float* cob   = (const float*)d_in[23];
    const float* l1w   = (const float*)d_in[24];
    const float* l1b   = (const float*)d_in[25];
    const float* l2w   = (const float*)d_in[26];
    const float* l2b   = (const float*)d_in[27];
    float* out = (float*)d_out;

    float *qkv, *t2, *offb, *awb, *sx, *sy, *sw, *val, *t3;
    __half *wts, *hmem, *hqin, *htgt, *ho, *hcain, *hca, *ht3, *hffn;
    cudaGetSymbolAddress((void**)&qkv,  g_qkv);
    cudaGetSymbolAddress((void**)&t2,   g_t2);
    cudaGetSymbolAddress((void**)&offb, g_off);
    cudaGetSymbolAddress((void**)&awb,  g_aw);
    cudaGetSymbolAddress((void**)&sx,   g_sx);
    cudaGetSymbolAddress((void**)&sy,   g_sy);
    cudaGetSymbolAddress((void**)&sw,   g_sw);
    cudaGetSymbolAddress((void**)&val,  g_val);
    cudaGetSymbolAddress((void**)&t3,   g_t3);
    cudaGetSymbolAddress((void**)&wts,  h_wts);
    cudaGetSymbolAddress((void**)&hmem, h_mem);
    cudaGetSymbolAddress((void**)&hqin, h_qin);
    cudaGetSymbolAddress((void**)&htgt, h_tgt);
    cudaGetSymbolAddress((void**)&ho,   h_o);
    cudaGetSymbolAddress((void**)&hcain,h_cain);
    cudaGetSymbolAddress((void**)&hca,  h_ca);
    cudaGetSymbolAddress((void**)&ht3,  h_t3);
    cudaGetSymbolAddress((void**)&hffn, h_ffn);

    static cudaStream_t s2 = nullptr;
    static cudaEvent_t ev_fork = nullptr, ev_join = nullptr;
    if (!s2) {
        cudaStreamCreateWithFlags(&s2, cudaStreamNonBlocking);
        cudaEventCreateWithFlags(&ev_fork, cudaEventDisableTiming);
        cudaEventCreateWithFlags(&ev_join, cudaEventDisableTiming);
        cudaFuncSetAttribute(gemm_h, cudaFuncAttributeMaxDynamicSharedMemorySize,
                             GEMM_SMEM);
    }

    auto gg = [](int N, int F) { return dim3((unsigned)(F / 128), (unsigned)((N + 127) / 128)); };
    const int n4 = NTOK * DMODEL / 4;
    const int m4 = MTOK * DMODEL / 4;

    // 0) weight + tgt conversions (needed by both branches)
    cvt_wts<<<(253952 + 255) / 256, 256>>>(
        (const float4*)in_w, (const float4*)sow, (const float4*)off_w,
        (const float4*)aw_w, (const float4*)val_w, (const float4*)cow,
        (const float4*)l1w, (const float4*)l2w, (__half2*)wts);
    cvt_kernel<<<(n4 + 255) / 256, 256>>>((const float4*)tgt, (__half2*)htgt, n4);

    // ---- fork: mem convert + val GEMM on s2 ----
    cudaEventRecord(ev_fork, 0);
    cudaStreamWaitEvent(s2, ev_fork, 0);
    cvt_kernel<<<(m4 + 255) / 256, 256, 0, s2>>>((const float4*)mem, (__half2*)hmem, m4);
    gemm_h<<<gg(MTOK, 256), 512, GEMM_SMEM, s2>>>(hmem, wts + HW_VALW, val_b, nullptr,
                                                  val, nullptr, MTOK, 256, 256, 256, 0, 0);
    cudaEventRecord(ev_join, s2);

    // ---- main chain ----
    add_kernel<<<(n4 + 255) / 256, 256>>>((const float4*)tgt, (const float4*)pos,
                                          (__half2*)hqin, n4);
    gemm_h<<<gg(NTOK, 512), 512, GEMM_SMEM>>>(hqin, wts + HW_INW, in_b, nullptr,
                                              qkv, nullptr, NTOK, 512, 256, 768, 0, 0);
    gemm_h<<<gg(NTOK, 256), 512, GEMM_SMEM>>>(htgt, wts + HW_INW + 512 * 256, in_b + 512,
                                              nullptr, qkv, nullptr, NTOK, 256, 256, 768, 512, 0);
    attn_kernel<<<dim3((NQ + 127) / 128, BATCH * HEADS), 128>>>(qkv, ho);
    gemm_h<<<gg(NTOK, 256), 512, GEMM_SMEM>>>(ho, wts + HW_SOW, sob, tgt,
                                              t2, nullptr, NTOK, 256, 256, 256, 0, 0);
    ln_kernel<<<(NTOK * 32 + 255) / 256, 256>>>(t2, n2g, n2b, NTOK, nullptr);
    add_kernel<<<(n4 + 255) / 256, 256>>>((const float4*)t2, (const float4*)pos,
                                          (__half2*)hcain, n4);
    gemm_h<<<gg(NTOK, 256), 512, GEMM_SMEM>>>(hcain, wts + HW_OFFW, off_b, nullptr,
                                              offb, nullptr, NTOK, 256, 256, 256, 0, 0);
    gemm_h<<<gg(NTOK, 128), 512, GEMM_SMEM>>>(hcain, wts + HW_AWW, aw_b, nullptr,
                                              awb, nullptr, NTOK, 128, 256, 128, 0, 0);
    prep_kernel<<<(NTOK * HEADS + 255) / 256, 256>>>(offb, awb, ref, sx, sy, sw);

    // ---- join: gather needs the val projection ----
    cudaStreamWaitEvent(0, ev_join, 0);

    gather_kernel<<<(NTOK * HEADS * 32 + 255) / 256, 256>>>(val, sx, sy, sw, hca);
    gemm_h<<<gg(NTOK, 256), 512, GEMM_SMEM>>>(hca, wts + HW_COW, cob, t2,
                                              t3, nullptr, NTOK, 256, 256, 256, 0, 0);
    ln_kernel<<<(NTOK * 32 + 255) / 256, 256>>>(t3, n1g, n1b, NTOK, ht3);
    gemm_h<<<gg(NTOK, 1024), 512, GEMM_SMEM>>>(ht3, wts + HW_L1W, l1b, nullptr,
                                               nullptr, hffn, NTOK, 1024, 256, 1024, 0, 1);
    gemm_h<<<gg(NTOK, 256), 512, GEMM_SMEM>>>(hffn, wts + HW_L2W, l2b, t3,
                                              out, nullptr, NTOK, 256, 1024, 256, 0, 0);
    ln_kernel<<<(NTOK * 32 + 255) / 256, 256>>>(out, n3g, n3b, NTOK, nullptr);
}